// round 12
// baseline (speedup 1.0000x reference)
#include <cuda_runtime.h>
#include <cuda_bf16.h>
#include <math.h>

#define N_NODES 50000
#define N_EDGES 400000
#define HDIM 64
#define EDIM 8
#define MHID 128
#define RHID 128
#define PB 64      // nodes per block in projection branch
#define GB 16      // nodes per block in fused GRU kernel (2 per warp)
#define MAXDEG 64  // ELL width; P(Poisson(8) >= 64) ~ 1e-36

typedef unsigned long long u64;

// Grid partition constants
#define NB_INIT  12500
#define NB_CORIG 12500
#define NB_PWG   48
#define NB_PPK   41
#define NB_ELL   1563
#define NB_PROJ  782

// Scratch (device globals: no allocation allowed)
__device__ float g_h[N_NODES * HDIM];
__device__ float g_PA[2][N_NODES * MHID];
__device__ float g_PBuf[2][N_NODES * MHID];
__device__ int   g_cnt[N_NODES];
__device__ int2  g_ell[(long)N_NODES * MAXDEG];
__device__ float g_C[(long)N_EDGES * MHID];
__device__ u64   g_Wg2[64 * 192];
__device__ u64   g_Whp[32 * 192];
__device__ u64   g_Wr1p[32 * 128];
__device__ float g_bvec[192];

__device__ __forceinline__ float sigmoidf(float x) { return 1.f / (1.f + expf(-x)); }
__device__ __forceinline__ u64 pack2(float lo, float hi) {
    u64 r; asm("mov.b64 %0, {%1, %2};" : "=l"(r) : "f"(lo), "f"(hi)); return r;
}
__device__ __forceinline__ void unpack2(u64 v, float& lo, float& hi) {
    asm("mov.b64 {%0, %1}, %2;" : "=f"(lo), "=f"(hi) : "l"(v));
}
__device__ __forceinline__ u64 fma2(u64 a, u64 b, u64 c) {
    u64 d; asm("fma.rn.f32x2 %0, %1, %2, %3;" : "=l"(d) : "l"(a), "l"(b), "l"(c)); return d;
}

// ---------------------------------------------------------------------------
// Launch 0: grid-partitioned init + C (original order) + weight prep.
// ---------------------------------------------------------------------------
__global__ __launch_bounds__(256) void mega_init_kernel(
    const float* __restrict__ nf, const float* __restrict__ ef,
    const float* __restrict__ W1, const float* __restrict__ b1,
    const float* __restrict__ W2, const float* __restrict__ Wx,
    const float* __restrict__ Wh, const float* __restrict__ Wr1,
    const float* __restrict__ b2)
{
    const int b   = blockIdx.x;
    const int tid = threadIdx.x;

    if (b < NB_INIT) {
        int i = b * 256 + tid;
        if (i < N_NODES * HDIM) g_h[i] = nf[i];
        if (i < N_NODES) g_cnt[i] = 0;
        return;
    }
    if (b < NB_INIT + NB_CORIG) {
        __shared__ float sW1c[EDIM][MHID];
        __shared__ float sb1[MHID];
        __shared__ float sef[32][EDIM];
        const int e0 = (b - NB_INIT) * 32;
        for (int i = tid; i < EDIM * MHID; i += 256)
            sW1c[i >> 7][i & 127] = W1[128 * MHID + i];
        if (tid < MHID) sb1[tid] = b1[tid];
        { int r = tid >> 3, k = tid & 7; sef[r][k] = ef[(long)(e0 + r) * EDIM + k]; }
        __syncthreads();

        const int r  = tid >> 3;
        const int c0 = (tid & 7) * 16;
        const long pos = e0 + r;
        float efr[EDIM];
        #pragma unroll
        for (int k = 0; k < EDIM; k++) efr[k] = sef[r][k];
        #pragma unroll
        for (int i = 0; i < 4; i++) {
            int c = c0 + 4 * i;
            float v0 = sb1[c], v1 = sb1[c + 1], v2 = sb1[c + 2], v3 = sb1[c + 3];
            #pragma unroll
            for (int k = 0; k < EDIM; k++) {
                float e_k = efr[k];
                v0 = fmaf(e_k, sW1c[k][c + 0], v0);
                v1 = fmaf(e_k, sW1c[k][c + 1], v1);
                v2 = fmaf(e_k, sW1c[k][c + 2], v2);
                v3 = fmaf(e_k, sW1c[k][c + 3], v3);
            }
            *reinterpret_cast<float4*>(g_C + pos * MHID + c) = make_float4(v0, v1, v2, v3);
        }
        return;
    }
    if (b < NB_INIT + NB_CORIG + NB_PWG) {
        int t = (b - (NB_INIT + NB_CORIG)) * 256 + tid;
        if (t < 64 * 192) {
            int k2 = t / 192, j = t % 192;
            float s0 = 0.f, s1 = 0.f;
            for (int c = 0; c < 64; c++) {
                float w = Wx[c * 192 + j];
                s0 = fmaf(W2[(2 * k2) * 64 + c], w, s0);
                s1 = fmaf(W2[(2 * k2 + 1) * 64 + c], w, s1);
            }
            g_Wg2[k2 * 192 + j] = pack2(s0, s1);
        }
        return;
    }
    {
        int t = (b - (NB_INIT + NB_CORIG + NB_PWG)) * 256 + tid;
        if (t < 32 * 192) {
            int i = t / 192, j = t % 192;
            g_Whp[t] = pack2(Wh[(2 * i) * 192 + j], Wh[(2 * i + 1) * 192 + j]);
        } else if (t < 32 * 192 + 32 * 128) {
            int u = t - 32 * 192;
            int i = u / 128, j = u % 128;
            g_Wr1p[u] = pack2(Wr1[(2 * i) * 128 + j], Wr1[(2 * i + 1) * 128 + j]);
        } else if (t < 32 * 192 + 32 * 128 + 192) {
            int j = t - (32 * 192 + 32 * 128);
            float s = 0.f;
            for (int c = 0; c < 64; c++) s = fmaf(b2[c], Wx[c * 192 + j], s);
            g_bvec[j] = s;
        }
    }
}

// ---------------------------------------------------------------------------
// Launch 1: ELL build + standalone projection into buffer 0.
// ---------------------------------------------------------------------------
__global__ __launch_bounds__(256) void build_proj_kernel(
    const int* __restrict__ src, const int* __restrict__ dst,
    const float* __restrict__ W1)
{
    const int b   = blockIdx.x;
    const int tid = threadIdx.x;

    if (b < NB_ELL) {
        int i = b * 256 + tid;
        if (i < N_EDGES) {
            int d = dst[i];
            int slot = atomicAdd(&g_cnt[d], 1);
            if (slot < MAXDEG)
                g_ell[(long)d * MAXDEG + slot] = make_int2(src[i], i);
        }
        return;
    }

    __shared__ float sh[PB][HDIM];
    const int n0 = (b - NB_ELL) * PB;

    for (int i = tid; i < PB * HDIM; i += 256) {
        int r = i >> 6, c = i & 63;
        int node = n0 + r;
        sh[r][c] = (node < N_NODES) ? g_h[(long)node * HDIM + c] : 0.f;
    }
    __syncthreads();

    const int hc = tid & 31;
    const int nr = tid >> 5;
    const int j0 = hc * 8;
    const float* Wbase = (j0 < 128) ? (W1 + j0) : (W1 + 64 * MHID + (j0 - 128));

    float acc[8][8];
    #pragma unroll
    for (int n = 0; n < 8; n++)
        #pragma unroll
        for (int j = 0; j < 8; j++) acc[n][j] = 0.f;

    #pragma unroll 2
    for (int k = 0; k < HDIM; k++) {
        const float4* wp = reinterpret_cast<const float4*>(Wbase + (long)k * MHID);
        float4 wA = wp[0], wB = wp[1];
        #pragma unroll
        for (int n = 0; n < 8; n++) {
            float a = sh[nr + 8 * n][k];
            acc[n][0] = fmaf(a, wA.x, acc[n][0]);
            acc[n][1] = fmaf(a, wA.y, acc[n][1]);
            acc[n][2] = fmaf(a, wA.z, acc[n][2]);
            acc[n][3] = fmaf(a, wA.w, acc[n][3]);
            acc[n][4] = fmaf(a, wB.x, acc[n][4]);
            acc[n][5] = fmaf(a, wB.y, acc[n][5]);
            acc[n][6] = fmaf(a, wB.z, acc[n][6]);
            acc[n][7] = fmaf(a, wB.w, acc[n][7]);
        }
    }

    #pragma unroll
    for (int n = 0; n < 8; n++) {
        int node = n0 + nr + 8 * n;
        if (node < N_NODES) {
            float* dstp = (j0 < 128) ? (g_PA[0] + (long)node * MHID + j0)
                                     : (g_PBuf[0] + (long)node * MHID + (j0 - 128));
            float4* op = reinterpret_cast<float4*>(dstp);
            op[0] = make_float4(acc[n][0], acc[n][1], acc[n][2], acc[n][3]);
            op[1] = make_float4(acc[n][4], acc[n][5], acc[n][6], acc[n][7]);
        }
    }
}

// ---------------------------------------------------------------------------
// Launches 2/3: ELL aggregation + gates GEMM + GRU + (proj | readout).
// GB=16 (2 nodes per warp) -> half the accumulator registers -> 4 CTAs/SM.
// ---------------------------------------------------------------------------
__global__ __launch_bounds__(256, 4) void gru_fused_kernel(
    const float* __restrict__ bg, const float* __restrict__ W1,
    const float* __restrict__ br1, const float* __restrict__ Wr2,
    const float* __restrict__ br2, float* __restrict__ out,
    int rbuf, int do_proj)
{
    __shared__ float sxh[GB][192];   // cols 0..127 agg128, 128..191 h_old
    const int tid  = threadIdx.x;
    const int lane = tid & 31;
    const int wid  = tid >> 5;
    const int n0   = blockIdx.x * GB;

    const float* PAr = g_PA[rbuf];
    const float* PBr = g_PBuf[rbuf];

    // --- ELL aggregation (warp-private rows, no atomics) ---
    int degn[2];
    #pragma unroll
    for (int n = 0; n < 2; n++) {
        const int r = wid + 8 * n;
        const int node = n0 + r;
        float4 acc = make_float4(0.f, 0.f, 0.f, 0.f);
        int dg = 0;
        if (node < N_NODES) {
            dg = g_cnt[node];
            if (dg > MAXDEG) dg = MAXDEG;
            float4 pb = *reinterpret_cast<const float4*>(PBr + (long)node * MHID + 4 * lane);
            const int2* ep = g_ell + (long)node * MAXDEG;
            for (int s = 0; s < dg; s++) {
                int2 e = ep[s];
                float4 pa = *reinterpret_cast<const float4*>(PAr + (long)e.x * MHID + 4 * lane);
                float4 cc = *reinterpret_cast<const float4*>(g_C + (long)e.y * MHID + 4 * lane);
                acc.x += fmaxf(pa.x + pb.x + cc.x, 0.f);
                acc.y += fmaxf(pa.y + pb.y + cc.y, 0.f);
                acc.z += fmaxf(pa.z + pb.z + cc.z, 0.f);
                acc.w += fmaxf(pa.w + pb.w + cc.w, 0.f);
            }
            float2 hv = *reinterpret_cast<const float2*>(g_h + (long)node * HDIM + 2 * lane);
            sxh[r][128 + 2 * lane]     = hv.x;
            sxh[r][128 + 2 * lane + 1] = hv.y;
        } else {
            sxh[r][128 + 2 * lane]     = 0.f;
            sxh[r][128 + 2 * lane + 1] = 0.f;
        }
        degn[n] = dg;
        *reinterpret_cast<float4*>(&sxh[r][4 * lane]) = acc;
    }
    __syncwarp();

    // --- gates GEMM: k-split f32x2 accumulators, 2 nodes ---
    u64 azr[2][4], acx[2][2], ach[2][2];
    #pragma unroll
    for (int n = 0; n < 2; n++) {
        #pragma unroll
        for (int j = 0; j < 4; j++) azr[n][j] = 0ull;
        acx[n][0] = acx[n][1] = 0ull;
        ach[n][0] = ach[n][1] = 0ull;
    }

    #pragma unroll 2
    for (int k2 = 0; k2 < 64; k2++) {        // agg128 @ WgA
        const u64* wr = g_Wg2 + k2 * 192;
        u64 wz0 = wr[lane],       wz1 = wr[lane + 32];
        u64 wr0 = wr[lane + 64],  wr1 = wr[lane + 96];
        u64 wc0 = wr[lane + 128], wc1 = wr[lane + 160];
        #pragma unroll
        for (int n = 0; n < 2; n++) {
            u64 a = *reinterpret_cast<const u64*>(&sxh[wid + 8 * n][2 * k2]);
            azr[n][0] = fma2(a, wz0, azr[n][0]);
            azr[n][1] = fma2(a, wz1, azr[n][1]);
            azr[n][2] = fma2(a, wr0, azr[n][2]);
            azr[n][3] = fma2(a, wr1, azr[n][3]);
            acx[n][0] = fma2(a, wc0, acx[n][0]);
            acx[n][1] = fma2(a, wc1, acx[n][1]);
        }
    }
    #pragma unroll 2
    for (int k2 = 0; k2 < 32; k2++) {        // h @ Wh
        const u64* wr = g_Whp + k2 * 192;
        u64 wz0 = wr[lane],       wz1 = wr[lane + 32];
        u64 wr0 = wr[lane + 64],  wr1 = wr[lane + 96];
        u64 wc0 = wr[lane + 128], wc1 = wr[lane + 160];
        #pragma unroll
        for (int n = 0; n < 2; n++) {
            u64 a = *reinterpret_cast<const u64*>(&sxh[wid + 8 * n][128 + 2 * k2]);
            azr[n][0] = fma2(a, wz0, azr[n][0]);
            azr[n][1] = fma2(a, wz1, azr[n][1]);
            azr[n][2] = fma2(a, wr0, azr[n][2]);
            azr[n][3] = fma2(a, wr1, azr[n][3]);
            ach[n][0] = fma2(a, wc0, ach[n][0]);
            ach[n][1] = fma2(a, wc1, ach[n][1]);
        }
    }

    // --- elementwise GRU ---
    {
        float bz[2] = { bg[lane],       bg[lane + 32] };
        float brg[2]= { bg[lane + 64],  bg[lane + 96] };
        float bc[2] = { bg[lane + 128], bg[lane + 160] };
        float vz[2] = { g_bvec[lane],       g_bvec[lane + 32] };
        float vr[2] = { g_bvec[lane + 64],  g_bvec[lane + 96] };
        float vc[2] = { g_bvec[lane + 128], g_bvec[lane + 160] };

        #pragma unroll
        for (int n = 0; n < 2; n++) {
            int r = wid + 8 * n;
            int node = n0 + r;
            float deg = (float)degn[n];
            #pragma unroll
            for (int j = 0; j < 2; j++) {
                int c = lane + 32 * j;
                float lo, hi, gz, gr, gcx, gch;
                unpack2(azr[n][j], lo, hi);     gz  = lo + hi;
                unpack2(azr[n][2 + j], lo, hi); gr  = lo + hi;
                unpack2(acx[n][j], lo, hi);     gcx = lo + hi;
                unpack2(ach[n][j], lo, hi);     gch = lo + hi;
                float z  = sigmoidf(gz + bz[j] + deg * vz[j]);
                float rr = sigmoidf(gr + brg[j] + deg * vr[j]);
                float hc = tanhf(gcx + bc[j] + deg * vc[j] + rr * gch);
                float hold = sxh[r][128 + c];
                float hnew = z * hold + (1.f - z) * hc;
                sxh[r][c] = hnew;
                if (node < N_NODES) g_h[(long)node * HDIM + c] = hnew;
            }
        }
    }
    __syncwarp();

    if (do_proj) {
        // PA/PB(rbuf^1) = h_new @ [W1a | W1b], col-pair f32x2
        float* PAw = g_PA[rbuf ^ 1];
        float* PBw = g_PBuf[rbuf ^ 1];
        u64 p[2][4];
        #pragma unroll
        for (int n = 0; n < 2; n++)
            #pragma unroll
            for (int j = 0; j < 4; j++) p[n][j] = 0ull;

        #pragma unroll 2
        for (int k = 0; k < 64; k++) {
            const float* w1r = W1 + (long)k * MHID;
            const float* w2r = W1 + (long)(64 + k) * MHID;
            u64 w0 = *reinterpret_cast<const u64*>(w1r + 2 * lane);
            u64 w1v= *reinterpret_cast<const u64*>(w1r + 64 + 2 * lane);
            u64 w2 = *reinterpret_cast<const u64*>(w2r + 2 * lane);
            u64 w3 = *reinterpret_cast<const u64*>(w2r + 64 + 2 * lane);
            #pragma unroll
            for (int n = 0; n < 2; n++) {
                float af = sxh[wid + 8 * n][k];
                u64 ap = pack2(af, af);
                p[n][0] = fma2(ap, w0, p[n][0]);
                p[n][1] = fma2(ap, w1v, p[n][1]);
                p[n][2] = fma2(ap, w2, p[n][2]);
                p[n][3] = fma2(ap, w3, p[n][3]);
            }
        }
        #pragma unroll
        for (int n = 0; n < 2; n++) {
            int node = n0 + wid + 8 * n;
            if (node < N_NODES) {
                float* pa = PAw + (long)node * MHID;
                float* pb = PBw + (long)node * MHID;
                *reinterpret_cast<u64*>(pa + 2 * lane)      = p[n][0];
                *reinterpret_cast<u64*>(pa + 64 + 2 * lane) = p[n][1];
                *reinterpret_cast<u64*>(pb + 2 * lane)      = p[n][2];
                *reinterpret_cast<u64*>(pb + 64 + 2 * lane) = p[n][3];
            }
        }
    } else {
        // readout: relu(h_new @ Wr1 + br1) @ Wr2 + br2 (k-split f32x2)
        u64 racc[2][4];
        #pragma unroll
        for (int n = 0; n < 2; n++)
            #pragma unroll
            for (int j = 0; j < 4; j++) racc[n][j] = 0ull;

        #pragma unroll 2
        for (int k2 = 0; k2 < 32; k2++) {
            const u64* wr = g_Wr1p + k2 * 128;
            u64 w0 = wr[lane],      w1v = wr[lane + 32];
            u64 w2 = wr[lane + 64], w3 = wr[lane + 96];
            #pragma unroll
            for (int n = 0; n < 2; n++) {
                u64 a = *reinterpret_cast<const u64*>(&sxh[wid + 8 * n][2 * k2]);
                racc[n][0] = fma2(a, w0, racc[n][0]);
                racc[n][1] = fma2(a, w1v, racc[n][1]);
                racc[n][2] = fma2(a, w2, racc[n][2]);
                racc[n][3] = fma2(a, w3, racc[n][3]);
            }
        }
        float bb[4], w2v[4];
        #pragma unroll
        for (int j = 0; j < 4; j++) {
            bb[j]  = br1[lane + 32 * j];
            w2v[j] = Wr2[lane + 32 * j];
        }
        float part[2];
        #pragma unroll
        for (int n = 0; n < 2; n++) {
            float s = 0.f;
            #pragma unroll
            for (int j = 0; j < 4; j++) {
                float lo, hi; unpack2(racc[n][j], lo, hi);
                float v = fmaxf(lo + hi + bb[j], 0.f);
                s = fmaf(v, w2v[j], s);
            }
            part[n] = s;
        }
        #pragma unroll
        for (int off = 16; off; off >>= 1)
            #pragma unroll
            for (int n = 0; n < 2; n++)
                part[n] += __shfl_xor_sync(0xffffffffu, part[n], off);
        if (lane == 0) {
            float bo = br2[0];
            #pragma unroll
            for (int n = 0; n < 2; n++) {
                int node = n0 + wid + 8 * n;
                if (node < N_NODES) out[node] = part[n] + bo;
            }
        }
    }
}

extern "C" void kernel_launch(void* const* d_in, const int* in_sizes, int n_in,
                              void* d_out, int out_size) {
    const float* nf  = (const float*)d_in[0];
    const float* ef  = (const float*)d_in[1];
    const int*   src = (const int*)  d_in[2];
    const int*   dst = (const int*)  d_in[3];
    const float* W1  = (const float*)d_in[4];
    const float* b1  = (const float*)d_in[5];
    const float* W2  = (const float*)d_in[6];
    const float* b2  = (const float*)d_in[7];
    const float* Wx  = (const float*)d_in[8];
    const float* Wh  = (const float*)d_in[9];
    const float* bg  = (const float*)d_in[10];
    const float* Wr1 = (const float*)d_in[11];
    const float* br1 = (const float*)d_in[12];
    const float* Wr2 = (const float*)d_in[13];
    const float* br2 = (const float*)d_in[14];
    float* out = (float*)d_out;

    const int ngru = (N_NODES + GB - 1) / GB;   // 3125

    // launch idx 0
    mega_init_kernel<<<NB_INIT + NB_CORIG + NB_PWG + NB_PPK, 256>>>(
        nf, ef, W1, b1, W2, Wx, Wh, Wr1, b2);
    // launch idx 1
    build_proj_kernel<<<NB_ELL + NB_PROJ, 256>>>(src, dst, W1);
    // launch idx 2: t = 0 (read buf0, write projections to buf1)
    gru_fused_kernel<<<ngru, 256>>>(bg, W1, br1, Wr2, br2, out, 0, 1);
    // launch idx 3: t = 1 (readout) — ncu capture slot
    gru_fused_kernel<<<ngru, 256>>>(bg, W1, br1, Wr2, br2, out, 1, 0);
}

// round 13
// speedup vs baseline: 1.1327x; 1.1327x over previous
#include <cuda_runtime.h>
#include <cuda_bf16.h>
#include <math.h>

#define N_NODES 50000
#define N_EDGES 400000
#define HDIM 64
#define EDIM 8
#define MHID 128
#define RHID 128
#define PB 64      // nodes per block in projection branch
#define GB 48      // nodes per block in fused GRU kernel (6 per warp)
#define MAXDEG 64  // ELL width; P(Poisson(8) >= 64) ~ 1e-36

typedef unsigned long long u64;

// Grid partition constants
#define NB_INIT  12500
#define NB_CORIG 12500
#define NB_PWG   48
#define NB_PPK   41
#define NB_ELL   1563
#define NB_PROJ  782

// Scratch (device globals: no allocation allowed)
__device__ float g_h[N_NODES * HDIM];
__device__ float g_PA[2][N_NODES * MHID];
__device__ float g_PBuf[2][N_NODES * MHID];
__device__ int   g_cnt[N_NODES];
__device__ int2  g_ell[(long)N_NODES * MAXDEG];
__device__ float g_C[(long)N_EDGES * MHID];
__device__ u64   g_Wg2[64 * 192];
__device__ u64   g_Whp[32 * 192];
__device__ u64   g_Wr1p[32 * 128];
__device__ float g_bvec[192];

__device__ __forceinline__ float sigmoidf(float x) { return 1.f / (1.f + expf(-x)); }
__device__ __forceinline__ u64 pack2(float lo, float hi) {
    u64 r; asm("mov.b64 %0, {%1, %2};" : "=l"(r) : "f"(lo), "f"(hi)); return r;
}
__device__ __forceinline__ void unpack2(u64 v, float& lo, float& hi) {
    asm("mov.b64 {%0, %1}, %2;" : "=f"(lo), "=f"(hi) : "l"(v));
}
__device__ __forceinline__ u64 fma2(u64 a, u64 b, u64 c) {
    u64 d; asm("fma.rn.f32x2 %0, %1, %2, %3;" : "=l"(d) : "l"(a), "l"(b), "l"(c)); return d;
}

// ---------------------------------------------------------------------------
// Launch 0: grid-partitioned init + C (original order) + weight prep.
// ---------------------------------------------------------------------------
__global__ __launch_bounds__(256) void mega_init_kernel(
    const float* __restrict__ nf, const float* __restrict__ ef,
    const float* __restrict__ W1, const float* __restrict__ b1,
    const float* __restrict__ W2, const float* __restrict__ Wx,
    const float* __restrict__ Wh, const float* __restrict__ Wr1,
    const float* __restrict__ b2)
{
    const int b   = blockIdx.x;
    const int tid = threadIdx.x;

    if (b < NB_INIT) {
        int i = b * 256 + tid;
        if (i < N_NODES * HDIM) g_h[i] = nf[i];
        if (i < N_NODES) g_cnt[i] = 0;
        return;
    }
    if (b < NB_INIT + NB_CORIG) {
        __shared__ float sW1c[EDIM][MHID];
        __shared__ float sb1[MHID];
        __shared__ float sef[32][EDIM];
        const int e0 = (b - NB_INIT) * 32;
        for (int i = tid; i < EDIM * MHID; i += 256)
            sW1c[i >> 7][i & 127] = W1[128 * MHID + i];
        if (tid < MHID) sb1[tid] = b1[tid];
        { int r = tid >> 3, k = tid & 7; sef[r][k] = ef[(long)(e0 + r) * EDIM + k]; }
        __syncthreads();

        const int r  = tid >> 3;
        const int c0 = (tid & 7) * 16;
        const long pos = e0 + r;
        float efr[EDIM];
        #pragma unroll
        for (int k = 0; k < EDIM; k++) efr[k] = sef[r][k];
        #pragma unroll
        for (int i = 0; i < 4; i++) {
            int c = c0 + 4 * i;
            float v0 = sb1[c], v1 = sb1[c + 1], v2 = sb1[c + 2], v3 = sb1[c + 3];
            #pragma unroll
            for (int k = 0; k < EDIM; k++) {
                float e_k = efr[k];
                v0 = fmaf(e_k, sW1c[k][c + 0], v0);
                v1 = fmaf(e_k, sW1c[k][c + 1], v1);
                v2 = fmaf(e_k, sW1c[k][c + 2], v2);
                v3 = fmaf(e_k, sW1c[k][c + 3], v3);
            }
            *reinterpret_cast<float4*>(g_C + pos * MHID + c) = make_float4(v0, v1, v2, v3);
        }
        return;
    }
    if (b < NB_INIT + NB_CORIG + NB_PWG) {
        int t = (b - (NB_INIT + NB_CORIG)) * 256 + tid;
        if (t < 64 * 192) {
            int k2 = t / 192, j = t % 192;
            float s0 = 0.f, s1 = 0.f;
            for (int c = 0; c < 64; c++) {
                float w = Wx[c * 192 + j];
                s0 = fmaf(W2[(2 * k2) * 64 + c], w, s0);
                s1 = fmaf(W2[(2 * k2 + 1) * 64 + c], w, s1);
            }
            g_Wg2[k2 * 192 + j] = pack2(s0, s1);
        }
        return;
    }
    {
        int t = (b - (NB_INIT + NB_CORIG + NB_PWG)) * 256 + tid;
        if (t < 32 * 192) {
            int i = t / 192, j = t % 192;
            g_Whp[t] = pack2(Wh[(2 * i) * 192 + j], Wh[(2 * i + 1) * 192 + j]);
        } else if (t < 32 * 192 + 32 * 128) {
            int u = t - 32 * 192;
            int i = u / 128, j = u % 128;
            g_Wr1p[u] = pack2(Wr1[(2 * i) * 128 + j], Wr1[(2 * i + 1) * 128 + j]);
        } else if (t < 32 * 192 + 32 * 128 + 192) {
            int j = t - (32 * 192 + 32 * 128);
            float s = 0.f;
            for (int c = 0; c < 64; c++) s = fmaf(b2[c], Wx[c * 192 + j], s);
            g_bvec[j] = s;
        }
    }
}

// ---------------------------------------------------------------------------
// Launch 1: ELL build + standalone projection into buffer 0.
// ---------------------------------------------------------------------------
__global__ __launch_bounds__(256) void build_proj_kernel(
    const int* __restrict__ src, const int* __restrict__ dst,
    const float* __restrict__ W1)
{
    const int b   = blockIdx.x;
    const int tid = threadIdx.x;

    if (b < NB_ELL) {
        int i = b * 256 + tid;
        if (i < N_EDGES) {
            int d = dst[i];
            int slot = atomicAdd(&g_cnt[d], 1);
            if (slot < MAXDEG)
                g_ell[(long)d * MAXDEG + slot] = make_int2(src[i], i);
        }
        return;
    }

    __shared__ float sh[PB][HDIM];
    const int n0 = (b - NB_ELL) * PB;

    for (int i = tid; i < PB * HDIM; i += 256) {
        int r = i >> 6, c = i & 63;
        int node = n0 + r;
        sh[r][c] = (node < N_NODES) ? g_h[(long)node * HDIM + c] : 0.f;
    }
    __syncthreads();

    const int hc = tid & 31;
    const int nr = tid >> 5;
    const int j0 = hc * 8;
    const float* Wbase = (j0 < 128) ? (W1 + j0) : (W1 + 64 * MHID + (j0 - 128));

    float acc[8][8];
    #pragma unroll
    for (int n = 0; n < 8; n++)
        #pragma unroll
        for (int j = 0; j < 8; j++) acc[n][j] = 0.f;

    #pragma unroll 2
    for (int k = 0; k < HDIM; k++) {
        const float4* wp = reinterpret_cast<const float4*>(Wbase + (long)k * MHID);
        float4 wA = wp[0], wB = wp[1];
        #pragma unroll
        for (int n = 0; n < 8; n++) {
            float a = sh[nr + 8 * n][k];
            acc[n][0] = fmaf(a, wA.x, acc[n][0]);
            acc[n][1] = fmaf(a, wA.y, acc[n][1]);
            acc[n][2] = fmaf(a, wA.z, acc[n][2]);
            acc[n][3] = fmaf(a, wA.w, acc[n][3]);
            acc[n][4] = fmaf(a, wB.x, acc[n][4]);
            acc[n][5] = fmaf(a, wB.y, acc[n][5]);
            acc[n][6] = fmaf(a, wB.z, acc[n][6]);
            acc[n][7] = fmaf(a, wB.w, acc[n][7]);
        }
    }

    #pragma unroll
    for (int n = 0; n < 8; n++) {
        int node = n0 + nr + 8 * n;
        if (node < N_NODES) {
            float* dstp = (j0 < 128) ? (g_PA[0] + (long)node * MHID + j0)
                                     : (g_PBuf[0] + (long)node * MHID + (j0 - 128));
            float4* op = reinterpret_cast<float4*>(dstp);
            op[0] = make_float4(acc[n][0], acc[n][1], acc[n][2], acc[n][3]);
            op[1] = make_float4(acc[n][4], acc[n][5], acc[n][6], acc[n][7]);
        }
    }
}

// ---------------------------------------------------------------------------
// Launches 2/3: ELL aggregation + gates GEMM + GRU + (proj | readout).
// GB=48: warp owns nodes {wid+8n, n=0..5} -> 6-way weight reuse.
// ---------------------------------------------------------------------------
__global__ __launch_bounds__(256, 2) void gru_fused_kernel(
    const float* __restrict__ bg, const float* __restrict__ W1,
    const float* __restrict__ br1, const float* __restrict__ Wr2,
    const float* __restrict__ br2, float* __restrict__ out,
    int rbuf, int do_proj)
{
    __shared__ float sxh[GB][192];   // cols 0..127 agg128, 128..191 h_old
    const int tid  = threadIdx.x;
    const int lane = tid & 31;
    const int wid  = tid >> 5;
    const int n0   = blockIdx.x * GB;

    const float* PAr = g_PA[rbuf];
    const float* PBr = g_PBuf[rbuf];

    // --- ELL aggregation (warp-private rows, no atomics) ---
    int degn[6];
    #pragma unroll
    for (int n = 0; n < 6; n++) {
        const int r = wid + 8 * n;
        const int node = n0 + r;
        float4 acc = make_float4(0.f, 0.f, 0.f, 0.f);
        int dg = 0;
        if (node < N_NODES) {
            dg = g_cnt[node];
            if (dg > MAXDEG) dg = MAXDEG;
            float4 pb = *reinterpret_cast<const float4*>(PBr + (long)node * MHID + 4 * lane);
            const int2* ep = g_ell + (long)node * MAXDEG;
            for (int s = 0; s < dg; s++) {
                int2 e = ep[s];
                float4 pa = *reinterpret_cast<const float4*>(PAr + (long)e.x * MHID + 4 * lane);
                float4 cc = *reinterpret_cast<const float4*>(g_C + (long)e.y * MHID + 4 * lane);
                acc.x += fmaxf(pa.x + pb.x + cc.x, 0.f);
                acc.y += fmaxf(pa.y + pb.y + cc.y, 0.f);
                acc.z += fmaxf(pa.z + pb.z + cc.z, 0.f);
                acc.w += fmaxf(pa.w + pb.w + cc.w, 0.f);
            }
            float2 hv = *reinterpret_cast<const float2*>(g_h + (long)node * HDIM + 2 * lane);
            sxh[r][128 + 2 * lane]     = hv.x;
            sxh[r][128 + 2 * lane + 1] = hv.y;
        } else {
            sxh[r][128 + 2 * lane]     = 0.f;
            sxh[r][128 + 2 * lane + 1] = 0.f;
        }
        degn[n] = dg;
        *reinterpret_cast<float4*>(&sxh[r][4 * lane]) = acc;
    }
    __syncwarp();

    // --- gates GEMM: k-split f32x2 accumulators, 6 nodes ---
    u64 azr[6][4], acx[6][2], ach[6][2];
    #pragma unroll
    for (int n = 0; n < 6; n++) {
        #pragma unroll
        for (int j = 0; j < 4; j++) azr[n][j] = 0ull;
        acx[n][0] = acx[n][1] = 0ull;
        ach[n][0] = ach[n][1] = 0ull;
    }

    for (int k2 = 0; k2 < 64; k2++) {        // agg128 @ WgA
        const u64* wr = g_Wg2 + k2 * 192;
        u64 wz0 = wr[lane],       wz1 = wr[lane + 32];
        u64 wr0 = wr[lane + 64],  wr1 = wr[lane + 96];
        u64 wc0 = wr[lane + 128], wc1 = wr[lane + 160];
        #pragma unroll
        for (int n = 0; n < 6; n++) {
            u64 a = *reinterpret_cast<const u64*>(&sxh[wid + 8 * n][2 * k2]);
            azr[n][0] = fma2(a, wz0, azr[n][0]);
            azr[n][1] = fma2(a, wz1, azr[n][1]);
            azr[n][2] = fma2(a, wr0, azr[n][2]);
            azr[n][3] = fma2(a, wr1, azr[n][3]);
            acx[n][0] = fma2(a, wc0, acx[n][0]);
            acx[n][1] = fma2(a, wc1, acx[n][1]);
        }
    }
    for (int k2 = 0; k2 < 32; k2++) {        // h @ Wh
        const u64* wr = g_Whp + k2 * 192;
        u64 wz0 = wr[lane],       wz1 = wr[lane + 32];
        u64 wr0 = wr[lane + 64],  wr1 = wr[lane + 96];
        u64 wc0 = wr[lane + 128], wc1 = wr[lane + 160];
        #pragma unroll
        for (int n = 0; n < 6; n++) {
            u64 a = *reinterpret_cast<const u64*>(&sxh[wid + 8 * n][128 + 2 * k2]);
            azr[n][0] = fma2(a, wz0, azr[n][0]);
            azr[n][1] = fma2(a, wz1, azr[n][1]);
            azr[n][2] = fma2(a, wr0, azr[n][2]);
            azr[n][3] = fma2(a, wr1, azr[n][3]);
            ach[n][0] = fma2(a, wc0, ach[n][0]);
            ach[n][1] = fma2(a, wc1, ach[n][1]);
        }
    }

    // --- elementwise GRU ---
    {
        float bz[2] = { bg[lane],       bg[lane + 32] };
        float brg[2]= { bg[lane + 64],  bg[lane + 96] };
        float bc[2] = { bg[lane + 128], bg[lane + 160] };
        float vz[2] = { g_bvec[lane],       g_bvec[lane + 32] };
        float vr[2] = { g_bvec[lane + 64],  g_bvec[lane + 96] };
        float vc[2] = { g_bvec[lane + 128], g_bvec[lane + 160] };

        #pragma unroll
        for (int n = 0; n < 6; n++) {
            int r = wid + 8 * n;
            int node = n0 + r;
            float deg = (float)degn[n];
            #pragma unroll
            for (int j = 0; j < 2; j++) {
                int c = lane + 32 * j;
                float lo, hi, gz, gr, gcx, gch;
                unpack2(azr[n][j], lo, hi);     gz  = lo + hi;
                unpack2(azr[n][2 + j], lo, hi); gr  = lo + hi;
                unpack2(acx[n][j], lo, hi);     gcx = lo + hi;
                unpack2(ach[n][j], lo, hi);     gch = lo + hi;
                float z  = sigmoidf(gz + bz[j] + deg * vz[j]);
                float rr = sigmoidf(gr + brg[j] + deg * vr[j]);
                float hc = tanhf(gcx + bc[j] + deg * vc[j] + rr * gch);
                float hold = sxh[r][128 + c];
                float hnew = z * hold + (1.f - z) * hc;
                sxh[r][c] = hnew;
                if (node < N_NODES) g_h[(long)node * HDIM + c] = hnew;
            }
        }
    }
    __syncwarp();

    if (do_proj) {
        // PA/PB(rbuf^1) = h_new @ [W1a | W1b], col-pair f32x2, 6 nodes
        float* PAw = g_PA[rbuf ^ 1];
        float* PBw = g_PBuf[rbuf ^ 1];
        u64 p[6][4];
        #pragma unroll
        for (int n = 0; n < 6; n++)
            #pragma unroll
            for (int j = 0; j < 4; j++) p[n][j] = 0ull;

        for (int k = 0; k < 64; k++) {
            const float* w1r = W1 + (long)k * MHID;
            const float* w2r = W1 + (long)(64 + k) * MHID;
            u64 w0 = *reinterpret_cast<const u64*>(w1r + 2 * lane);
            u64 w1v= *reinterpret_cast<const u64*>(w1r + 64 + 2 * lane);
            u64 w2 = *reinterpret_cast<const u64*>(w2r + 2 * lane);
            u64 w3 = *reinterpret_cast<const u64*>(w2r + 64 + 2 * lane);
            #pragma unroll
            for (int n = 0; n < 6; n++) {
                float af = sxh[wid + 8 * n][k];
                u64 ap = pack2(af, af);
                p[n][0] = fma2(ap, w0, p[n][0]);
                p[n][1] = fma2(ap, w1v, p[n][1]);
                p[n][2] = fma2(ap, w2, p[n][2]);
                p[n][3] = fma2(ap, w3, p[n][3]);
            }
        }
        #pragma unroll
        for (int n = 0; n < 6; n++) {
            int node = n0 + wid + 8 * n;
            if (node < N_NODES) {
                float* pa = PAw + (long)node * MHID;
                float* pb = PBw + (long)node * MHID;
                *reinterpret_cast<u64*>(pa + 2 * lane)      = p[n][0];
                *reinterpret_cast<u64*>(pa + 64 + 2 * lane) = p[n][1];
                *reinterpret_cast<u64*>(pb + 2 * lane)      = p[n][2];
                *reinterpret_cast<u64*>(pb + 64 + 2 * lane) = p[n][3];
            }
        }
    } else {
        // readout: relu(h_new @ Wr1 + br1) @ Wr2 + br2 (k-split f32x2), 6 nodes
        u64 racc[6][4];
        #pragma unroll
        for (int n = 0; n < 6; n++)
            #pragma unroll
            for (int j = 0; j < 4; j++) racc[n][j] = 0ull;

        for (int k2 = 0; k2 < 32; k2++) {
            const u64* wr = g_Wr1p + k2 * 128;
            u64 w0 = wr[lane],      w1v = wr[lane + 32];
            u64 w2 = wr[lane + 64], w3 = wr[lane + 96];
            #pragma unroll
            for (int n = 0; n < 6; n++) {
                u64 a = *reinterpret_cast<const u64*>(&sxh[wid + 8 * n][2 * k2]);
                racc[n][0] = fma2(a, w0, racc[n][0]);
                racc[n][1] = fma2(a, w1v, racc[n][1]);
                racc[n][2] = fma2(a, w2, racc[n][2]);
                racc[n][3] = fma2(a, w3, racc[n][3]);
            }
        }
        float bb[4], w2v[4];
        #pragma unroll
        for (int j = 0; j < 4; j++) {
            bb[j]  = br1[lane + 32 * j];
            w2v[j] = Wr2[lane + 32 * j];
        }
        float part[6];
        #pragma unroll
        for (int n = 0; n < 6; n++) {
            float s = 0.f;
            #pragma unroll
            for (int j = 0; j < 4; j++) {
                float lo, hi; unpack2(racc[n][j], lo, hi);
                float v = fmaxf(lo + hi + bb[j], 0.f);
                s = fmaf(v, w2v[j], s);
            }
            part[n] = s;
        }
        #pragma unroll
        for (int off = 16; off; off >>= 1)
            #pragma unroll
            for (int n = 0; n < 6; n++)
                part[n] += __shfl_xor_sync(0xffffffffu, part[n], off);
        if (lane == 0) {
            float bo = br2[0];
            #pragma unroll
            for (int n = 0; n < 6; n++) {
                int node = n0 + wid + 8 * n;
                if (node < N_NODES) out[node] = part[n] + bo;
            }
        }
    }
}

extern "C" void kernel_launch(void* const* d_in, const int* in_sizes, int n_in,
                              void* d_out, int out_size) {
    const float* nf  = (const float*)d_in[0];
    const float* ef  = (const float*)d_in[1];
    const int*   src = (const int*)  d_in[2];
    const int*   dst = (const int*)  d_in[3];
    const float* W1  = (const float*)d_in[4];
    const float* b1  = (const float*)d_in[5];
    const float* W2  = (const float*)d_in[6];
    const float* b2  = (const float*)d_in[7];
    const float* Wx  = (const float*)d_in[8];
    const float* Wh  = (const float*)d_in[9];
    const float* bg  = (const float*)d_in[10];
    const float* Wr1 = (const float*)d_in[11];
    const float* br1 = (const float*)d_in[12];
    const float* Wr2 = (const float*)d_in[13];
    const float* br2 = (const float*)d_in[14];
    float* out = (float*)d_out;

    const int ngru = (N_NODES + GB - 1) / GB;   // 1042

    // launch idx 0
    mega_init_kernel<<<NB_INIT + NB_CORIG + NB_PWG + NB_PPK, 256>>>(
        nf, ef, W1, b1, W2, Wx, Wh, Wr1, b2);
    // launch idx 1
    build_proj_kernel<<<NB_ELL + NB_PROJ, 256>>>(src, dst, W1);
    // launch idx 2: t = 0 (read buf0, write projections to buf1)
    gru_fused_kernel<<<ngru, 256>>>(bg, W1, br1, Wr2, br2, out, 0, 1);
    // launch idx 3: t = 1 (readout) — ncu capture slot
    gru_fused_kernel<<<ngru, 256>>>(bg, W1, br1, Wr2, br2, out, 1, 0);
}

// round 14
// speedup vs baseline: 1.2623x; 1.1145x over previous
#include <cuda_runtime.h>
#include <cuda_bf16.h>
#include <math.h>

#define N_NODES 50000
#define N_EDGES 400000
#define HDIM 64
#define EDIM 8
#define MHID 128
#define RHID 128
#define PB 64      // nodes per block in projection branch
#define GB 32      // nodes per block in GEMM/GRU kernel (4 per warp)
#define MAXDEG 64  // ELL width; P(Poisson(8) >= 64) ~ 1e-36

typedef unsigned long long u64;

// Grid partition constants
#define NB_INIT  12500
#define NB_CORIG 12500
#define NB_PWG   48
#define NB_PPK   41
#define NB_ELL   1563
#define NB_PROJ  782

// Scratch (device globals: no allocation allowed)
__device__ float g_h[N_NODES * HDIM];
__device__ float g_PA[2][N_NODES * MHID];
__device__ float g_PBuf[2][N_NODES * MHID];
__device__ float g_agg[N_NODES * MHID];
__device__ int   g_cnt[N_NODES];
__device__ int2  g_ell[(long)N_NODES * MAXDEG];
__device__ float g_C[(long)N_EDGES * MHID];
__device__ u64   g_Wg2[64 * 192];
__device__ u64   g_Whp[32 * 192];
__device__ u64   g_Wr1p[32 * 128];
__device__ float g_bvec[192];

__device__ __forceinline__ float sigmoidf(float x) { return 1.f / (1.f + expf(-x)); }
__device__ __forceinline__ u64 pack2(float lo, float hi) {
    u64 r; asm("mov.b64 %0, {%1, %2};" : "=l"(r) : "f"(lo), "f"(hi)); return r;
}
__device__ __forceinline__ void unpack2(u64 v, float& lo, float& hi) {
    asm("mov.b64 {%0, %1}, %2;" : "=f"(lo), "=f"(hi) : "l"(v));
}
__device__ __forceinline__ u64 fma2(u64 a, u64 b, u64 c) {
    u64 d; asm("fma.rn.f32x2 %0, %1, %2, %3;" : "=l"(d) : "l"(a), "l"(b), "l"(c)); return d;
}

// ---------------------------------------------------------------------------
// Launch 0: grid-partitioned init + C (original order) + weight prep.
// ---------------------------------------------------------------------------
__global__ __launch_bounds__(256) void mega_init_kernel(
    const float* __restrict__ nf, const float* __restrict__ ef,
    const float* __restrict__ W1, const float* __restrict__ b1,
    const float* __restrict__ W2, const float* __restrict__ Wx,
    const float* __restrict__ Wh, const float* __restrict__ Wr1,
    const float* __restrict__ b2)
{
    const int b   = blockIdx.x;
    const int tid = threadIdx.x;

    if (b < NB_INIT) {
        int i = b * 256 + tid;
        if (i < N_NODES * HDIM) g_h[i] = nf[i];
        if (i < N_NODES) g_cnt[i] = 0;
        return;
    }
    if (b < NB_INIT + NB_CORIG) {
        __shared__ float sW1c[EDIM][MHID];
        __shared__ float sb1[MHID];
        __shared__ float sef[32][EDIM];
        const int e0 = (b - NB_INIT) * 32;
        for (int i = tid; i < EDIM * MHID; i += 256)
            sW1c[i >> 7][i & 127] = W1[128 * MHID + i];
        if (tid < MHID) sb1[tid] = b1[tid];
        { int r = tid >> 3, k = tid & 7; sef[r][k] = ef[(long)(e0 + r) * EDIM + k]; }
        __syncthreads();

        const int r  = tid >> 3;
        const int c0 = (tid & 7) * 16;
        const long pos = e0 + r;
        float efr[EDIM];
        #pragma unroll
        for (int k = 0; k < EDIM; k++) efr[k] = sef[r][k];
        #pragma unroll
        for (int i = 0; i < 4; i++) {
            int c = c0 + 4 * i;
            float v0 = sb1[c], v1 = sb1[c + 1], v2 = sb1[c + 2], v3 = sb1[c + 3];
            #pragma unroll
            for (int k = 0; k < EDIM; k++) {
                float e_k = efr[k];
                v0 = fmaf(e_k, sW1c[k][c + 0], v0);
                v1 = fmaf(e_k, sW1c[k][c + 1], v1);
                v2 = fmaf(e_k, sW1c[k][c + 2], v2);
                v3 = fmaf(e_k, sW1c[k][c + 3], v3);
            }
            *reinterpret_cast<float4*>(g_C + pos * MHID + c) = make_float4(v0, v1, v2, v3);
        }
        return;
    }
    if (b < NB_INIT + NB_CORIG + NB_PWG) {
        int t = (b - (NB_INIT + NB_CORIG)) * 256 + tid;
        if (t < 64 * 192) {
            int k2 = t / 192, j = t % 192;
            float s0 = 0.f, s1 = 0.f;
            for (int c = 0; c < 64; c++) {
                float w = Wx[c * 192 + j];
                s0 = fmaf(W2[(2 * k2) * 64 + c], w, s0);
                s1 = fmaf(W2[(2 * k2 + 1) * 64 + c], w, s1);
            }
            g_Wg2[k2 * 192 + j] = pack2(s0, s1);
        }
        return;
    }
    {
        int t = (b - (NB_INIT + NB_CORIG + NB_PWG)) * 256 + tid;
        if (t < 32 * 192) {
            int i = t / 192, j = t % 192;
            g_Whp[t] = pack2(Wh[(2 * i) * 192 + j], Wh[(2 * i + 1) * 192 + j]);
        } else if (t < 32 * 192 + 32 * 128) {
            int u = t - 32 * 192;
            int i = u / 128, j = u % 128;
            g_Wr1p[u] = pack2(Wr1[(2 * i) * 128 + j], Wr1[(2 * i + 1) * 128 + j]);
        } else if (t < 32 * 192 + 32 * 128 + 192) {
            int j = t - (32 * 192 + 32 * 128);
            float s = 0.f;
            for (int c = 0; c < 64; c++) s = fmaf(b2[c], Wx[c * 192 + j], s);
            g_bvec[j] = s;
        }
    }
}

// ---------------------------------------------------------------------------
// Launch 1: ELL build + standalone projection into buffer 0.
// ---------------------------------------------------------------------------
__global__ __launch_bounds__(256) void build_proj_kernel(
    const int* __restrict__ src, const int* __restrict__ dst,
    const float* __restrict__ W1)
{
    const int b   = blockIdx.x;
    const int tid = threadIdx.x;

    if (b < NB_ELL) {
        int i = b * 256 + tid;
        if (i < N_EDGES) {
            int d = dst[i];
            int slot = atomicAdd(&g_cnt[d], 1);
            if (slot < MAXDEG)
                g_ell[(long)d * MAXDEG + slot] = make_int2(src[i], i);
        }
        return;
    }

    __shared__ float sh[PB][HDIM];
    const int n0 = (b - NB_ELL) * PB;

    for (int i = tid; i < PB * HDIM; i += 256) {
        int r = i >> 6, c = i & 63;
        int node = n0 + r;
        sh[r][c] = (node < N_NODES) ? g_h[(long)node * HDIM + c] : 0.f;
    }
    __syncthreads();

    const int hc = tid & 31;
    const int nr = tid >> 5;
    const int j0 = hc * 8;
    const float* Wbase = (j0 < 128) ? (W1 + j0) : (W1 + 64 * MHID + (j0 - 128));

    float acc[8][8];
    #pragma unroll
    for (int n = 0; n < 8; n++)
        #pragma unroll
        for (int j = 0; j < 8; j++) acc[n][j] = 0.f;

    #pragma unroll 2
    for (int k = 0; k < HDIM; k++) {
        const float4* wp = reinterpret_cast<const float4*>(Wbase + (long)k * MHID);
        float4 wA = wp[0], wB = wp[1];
        #pragma unroll
        for (int n = 0; n < 8; n++) {
            float a = sh[nr + 8 * n][k];
            acc[n][0] = fmaf(a, wA.x, acc[n][0]);
            acc[n][1] = fmaf(a, wA.y, acc[n][1]);
            acc[n][2] = fmaf(a, wA.z, acc[n][2]);
            acc[n][3] = fmaf(a, wA.w, acc[n][3]);
            acc[n][4] = fmaf(a, wB.x, acc[n][4]);
            acc[n][5] = fmaf(a, wB.y, acc[n][5]);
            acc[n][6] = fmaf(a, wB.z, acc[n][6]);
            acc[n][7] = fmaf(a, wB.w, acc[n][7]);
        }
    }

    #pragma unroll
    for (int n = 0; n < 8; n++) {
        int node = n0 + nr + 8 * n;
        if (node < N_NODES) {
            float* dstp = (j0 < 128) ? (g_PA[0] + (long)node * MHID + j0)
                                     : (g_PBuf[0] + (long)node * MHID + (j0 - 128));
            float4* op = reinterpret_cast<float4*>(dstp);
            op[0] = make_float4(acc[n][0], acc[n][1], acc[n][2], acc[n][3]);
            op[1] = make_float4(acc[n][4], acc[n][5], acc[n][6], acc[n][7]);
        }
    }
}

// ---------------------------------------------------------------------------
// Kernel A: ELL aggregation only. One warp per node, lightweight -> high occ.
//   agg[d] = sum_e relu(PA[src_e] + PB[d] + C[e])
// ---------------------------------------------------------------------------
__global__ __launch_bounds__(256) void agg_kernel(int rbuf) {
    const int lane = threadIdx.x & 31;
    const int wid  = threadIdx.x >> 5;
    const int node = blockIdx.x * 8 + wid;
    if (node >= N_NODES) return;

    const float* PAr = g_PA[rbuf];
    const float* PBr = g_PBuf[rbuf];

    int dg = g_cnt[node];
    if (dg > MAXDEG) dg = MAXDEG;

    float4 pb = *reinterpret_cast<const float4*>(PBr + (long)node * MHID + 4 * lane);
    float4 acc = make_float4(0.f, 0.f, 0.f, 0.f);
    const int2* ep = g_ell + (long)node * MAXDEG;

    for (int s = 0; s < dg; s++) {
        int2 e = ep[s];
        float4 pa = *reinterpret_cast<const float4*>(PAr + (long)e.x * MHID + 4 * lane);
        float4 cc = *reinterpret_cast<const float4*>(g_C + (long)e.y * MHID + 4 * lane);
        acc.x += fmaxf(pa.x + pb.x + cc.x, 0.f);
        acc.y += fmaxf(pa.y + pb.y + cc.y, 0.f);
        acc.z += fmaxf(pa.z + pb.z + cc.z, 0.f);
        acc.w += fmaxf(pa.w + pb.w + cc.w, 0.f);
    }
    *reinterpret_cast<float4*>(g_agg + (long)node * MHID + 4 * lane) = acc;
}

// ---------------------------------------------------------------------------
// Kernel B: gates GEMM + GRU + (proj | readout). R11 config (4 nodes/warp).
// ---------------------------------------------------------------------------
__global__ __launch_bounds__(256, 2) void gru_fused_kernel(
    const float* __restrict__ bg, const float* __restrict__ W1,
    const float* __restrict__ br1, const float* __restrict__ Wr2,
    const float* __restrict__ br2, float* __restrict__ out,
    int rbuf, int do_proj)
{
    __shared__ float sxh[GB][192];   // cols 0..127 agg128, 128..191 h_old
    const int tid  = threadIdx.x;
    const int lane = tid & 31;
    const int wid  = tid >> 5;
    const int n0   = blockIdx.x * GB;

    // --- stage agg + h (coalesced loads; no gather stalls here) ---
    int degn[4];
    #pragma unroll
    for (int n = 0; n < 4; n++) {
        const int r = wid + 8 * n;
        const int node = n0 + r;
        if (node < N_NODES) {
            *reinterpret_cast<float4*>(&sxh[r][4 * lane]) =
                *reinterpret_cast<const float4*>(g_agg + (long)node * MHID + 4 * lane);
            float2 hv = *reinterpret_cast<const float2*>(g_h + (long)node * HDIM + 2 * lane);
            sxh[r][128 + 2 * lane]     = hv.x;
            sxh[r][128 + 2 * lane + 1] = hv.y;
            degn[n] = min(g_cnt[node], MAXDEG);
        } else {
            *reinterpret_cast<float4*>(&sxh[r][4 * lane]) = make_float4(0.f, 0.f, 0.f, 0.f);
            sxh[r][128 + 2 * lane]     = 0.f;
            sxh[r][128 + 2 * lane + 1] = 0.f;
            degn[n] = 0;
        }
    }
    __syncwarp();

    // --- gates GEMM: k-split f32x2 accumulators ---
    u64 azr[4][4], acx[4][2], ach[4][2];
    #pragma unroll
    for (int n = 0; n < 4; n++) {
        #pragma unroll
        for (int j = 0; j < 4; j++) azr[n][j] = 0ull;
        acx[n][0] = acx[n][1] = 0ull;
        ach[n][0] = ach[n][1] = 0ull;
    }

    #pragma unroll 2
    for (int k2 = 0; k2 < 64; k2++) {        // agg128 @ WgA
        const u64* wr = g_Wg2 + k2 * 192;
        u64 wz0 = wr[lane],       wz1 = wr[lane + 32];
        u64 wr0 = wr[lane + 64],  wr1 = wr[lane + 96];
        u64 wc0 = wr[lane + 128], wc1 = wr[lane + 160];
        #pragma unroll
        for (int n = 0; n < 4; n++) {
            u64 a = *reinterpret_cast<const u64*>(&sxh[wid + 8 * n][2 * k2]);
            azr[n][0] = fma2(a, wz0, azr[n][0]);
            azr[n][1] = fma2(a, wz1, azr[n][1]);
            azr[n][2] = fma2(a, wr0, azr[n][2]);
            azr[n][3] = fma2(a, wr1, azr[n][3]);
            acx[n][0] = fma2(a, wc0, acx[n][0]);
            acx[n][1] = fma2(a, wc1, acx[n][1]);
        }
    }
    #pragma unroll 2
    for (int k2 = 0; k2 < 32; k2++) {        // h @ Wh
        const u64* wr = g_Whp + k2 * 192;
        u64 wz0 = wr[lane],       wz1 = wr[lane + 32];
        u64 wr0 = wr[lane + 64],  wr1 = wr[lane + 96];
        u64 wc0 = wr[lane + 128], wc1 = wr[lane + 160];
        #pragma unroll
        for (int n = 0; n < 4; n++) {
            u64 a = *reinterpret_cast<const u64*>(&sxh[wid + 8 * n][128 + 2 * k2]);
            azr[n][0] = fma2(a, wz0, azr[n][0]);
            azr[n][1] = fma2(a, wz1, azr[n][1]);
            azr[n][2] = fma2(a, wr0, azr[n][2]);
            azr[n][3] = fma2(a, wr1, azr[n][3]);
            ach[n][0] = fma2(a, wc0, ach[n][0]);
            ach[n][1] = fma2(a, wc1, ach[n][1]);
        }
    }

    // --- elementwise GRU ---
    {
        float bz[2] = { bg[lane],       bg[lane + 32] };
        float brg[2]= { bg[lane + 64],  bg[lane + 96] };
        float bc[2] = { bg[lane + 128], bg[lane + 160] };
        float vz[2] = { g_bvec[lane],       g_bvec[lane + 32] };
        float vr[2] = { g_bvec[lane + 64],  g_bvec[lane + 96] };
        float vc[2] = { g_bvec[lane + 128], g_bvec[lane + 160] };

        #pragma unroll
        for (int n = 0; n < 4; n++) {
            int r = wid + 8 * n;
            int node = n0 + r;
            float deg = (float)degn[n];
            #pragma unroll
            for (int j = 0; j < 2; j++) {
                int c = lane + 32 * j;
                float lo, hi, gz, gr, gcx, gch;
                unpack2(azr[n][j], lo, hi);     gz  = lo + hi;
                unpack2(azr[n][2 + j], lo, hi); gr  = lo + hi;
                unpack2(acx[n][j], lo, hi);     gcx = lo + hi;
                unpack2(ach[n][j], lo, hi);     gch = lo + hi;
                float z  = sigmoidf(gz + bz[j] + deg * vz[j]);
                float rr = sigmoidf(gr + brg[j] + deg * vr[j]);
                float hc = tanhf(gcx + bc[j] + deg * vc[j] + rr * gch);
                float hold = sxh[r][128 + c];
                float hnew = z * hold + (1.f - z) * hc;
                sxh[r][c] = hnew;
                if (node < N_NODES) g_h[(long)node * HDIM + c] = hnew;
            }
        }
    }
    __syncwarp();

    if (do_proj) {
        float* PAw = g_PA[rbuf ^ 1];
        float* PBw = g_PBuf[rbuf ^ 1];
        u64 p[4][4];
        #pragma unroll
        for (int n = 0; n < 4; n++)
            #pragma unroll
            for (int j = 0; j < 4; j++) p[n][j] = 0ull;

        #pragma unroll 2
        for (int k = 0; k < 64; k++) {
            const float* w1r = W1 + (long)k * MHID;
            const float* w2r = W1 + (long)(64 + k) * MHID;
            u64 w0 = *reinterpret_cast<const u64*>(w1r + 2 * lane);
            u64 w1v= *reinterpret_cast<const u64*>(w1r + 64 + 2 * lane);
            u64 w2 = *reinterpret_cast<const u64*>(w2r + 2 * lane);
            u64 w3 = *reinterpret_cast<const u64*>(w2r + 64 + 2 * lane);
            #pragma unroll
            for (int n = 0; n < 4; n++) {
                float af = sxh[wid + 8 * n][k];
                u64 ap = pack2(af, af);
                p[n][0] = fma2(ap, w0, p[n][0]);
                p[n][1] = fma2(ap, w1v, p[n][1]);
                p[n][2] = fma2(ap, w2, p[n][2]);
                p[n][3] = fma2(ap, w3, p[n][3]);
            }
        }
        #pragma unroll
        for (int n = 0; n < 4; n++) {
            int node = n0 + wid + 8 * n;
            if (node < N_NODES) {
                float* pa = PAw + (long)node * MHID;
                float* pb = PBw + (long)node * MHID;
                *reinterpret_cast<u64*>(pa + 2 * lane)      = p[n][0];
                *reinterpret_cast<u64*>(pa + 64 + 2 * lane) = p[n][1];
                *reinterpret_cast<u64*>(pb + 2 * lane)      = p[n][2];
                *reinterpret_cast<u64*>(pb + 64 + 2 * lane) = p[n][3];
            }
        }
    } else {
        u64 racc[4][4];
        #pragma unroll
        for (int n = 0; n < 4; n++)
            #pragma unroll
            for (int j = 0; j < 4; j++) racc[n][j] = 0ull;

        #pragma unroll 2
        for (int k2 = 0; k2 < 32; k2++) {
            const u64* wr = g_Wr1p + k2 * 128;
            u64 w0 = wr[lane],      w1v = wr[lane + 32];
            u64 w2 = wr[lane + 64], w3 = wr[lane + 96];
            #pragma unroll
            for (int n = 0; n < 4; n++) {
                u64 a = *reinterpret_cast<const u64*>(&sxh[wid + 8 * n][2 * k2]);
                racc[n][0] = fma2(a, w0, racc[n][0]);
                racc[n][1] = fma2(a, w1v, racc[n][1]);
                racc[n][2] = fma2(a, w2, racc[n][2]);
                racc[n][3] = fma2(a, w3, racc[n][3]);
            }
        }
        float bb[4], w2v[4];
        #pragma unroll
        for (int j = 0; j < 4; j++) {
            bb[j]  = br1[lane + 32 * j];
            w2v[j] = Wr2[lane + 32 * j];
        }
        float part[4];
        #pragma unroll
        for (int n = 0; n < 4; n++) {
            float s = 0.f;
            #pragma unroll
            for (int j = 0; j < 4; j++) {
                float lo, hi; unpack2(racc[n][j], lo, hi);
                float v = fmaxf(lo + hi + bb[j], 0.f);
                s = fmaf(v, w2v[j], s);
            }
            part[n] = s;
        }
        #pragma unroll
        for (int off = 16; off; off >>= 1)
            #pragma unroll
            for (int n = 0; n < 4; n++)
                part[n] += __shfl_xor_sync(0xffffffffu, part[n], off);
        if (lane == 0) {
            float bo = br2[0];
            #pragma unroll
            for (int n = 0; n < 4; n++) {
                int node = n0 + wid + 8 * n;
                if (node < N_NODES) out[node] = part[n] + bo;
            }
        }
    }
}

extern "C" void kernel_launch(void* const* d_in, const int* in_sizes, int n_in,
                              void* d_out, int out_size) {
    const float* nf  = (const float*)d_in[0];
    const float* ef  = (const float*)d_in[1];
    const int*   src = (const int*)  d_in[2];
    const int*   dst = (const int*)  d_in[3];
    const float* W1  = (const float*)d_in[4];
    const float* b1  = (const float*)d_in[5];
    const float* W2  = (const float*)d_in[6];
    const float* b2  = (const float*)d_in[7];
    const float* Wx  = (const float*)d_in[8];
    const float* Wh  = (const float*)d_in[9];
    const float* bg  = (const float*)d_in[10];
    const float* Wr1 = (const float*)d_in[11];
    const float* br1 = (const float*)d_in[12];
    const float* Wr2 = (const float*)d_in[13];
    const float* br2 = (const float*)d_in[14];
    float* out = (float*)d_out;

    const int ngru = (N_NODES + GB - 1) / GB;      // 1563
    const int nagg = (N_NODES + 7) / 8;            // 6250

    // launch idx 0
    mega_init_kernel<<<NB_INIT + NB_CORIG + NB_PWG + NB_PPK, 256>>>(
        nf, ef, W1, b1, W2, Wx, Wh, Wr1, b2);
    // launch idx 1
    build_proj_kernel<<<NB_ELL + NB_PROJ, 256>>>(src, dst, W1);
    // t = 0
    agg_kernel<<<nagg, 256>>>(0);                              // idx 2
    gru_fused_kernel<<<ngru, 256>>>(bg, W1, br1, Wr2, br2, out, 0, 1);  // idx 3 (ncu slot)
    // t = 1
    agg_kernel<<<nagg, 256>>>(1);                              // idx 4
    gru_fused_kernel<<<ngru, 256>>>(bg, W1, br1, Wr2, br2, out, 1, 0);  // idx 5
}

// round 15
// speedup vs baseline: 1.6182x; 1.2819x over previous
#include <cuda_runtime.h>
#include <cuda_bf16.h>
#include <math.h>

#define N_NODES 50000
#define N_EDGES 400000
#define HDIM 64
#define EDIM 8
#define MHID 128
#define RHID 128
#define PB 64      // nodes per block in projection branch
#define GB 32      // nodes per block in GEMM/GRU kernel (8 per warp-pair)
#define MAXDEG 64  // ELL width; P(Poisson(8) >= 64) ~ 1e-36

typedef unsigned long long u64;

// Grid partition constants
#define NB_INIT  12500
#define NB_PWG   48
#define NB_PPK   41
#define NB_ELL   1563
#define NB_PROJ  782

// Scratch (device globals: no allocation allowed)
__device__ float g_h[N_NODES * HDIM];
__device__ float g_PA[2][N_NODES * MHID];
__device__ float g_PBuf[2][N_NODES * MHID];
__device__ float g_agg[N_NODES * MHID];
__device__ int   g_cnt[N_NODES];
__device__ int2  g_ell[(long)N_NODES * MAXDEG];   // (src, edge_id)
__device__ u64   g_Wg2[64 * 192];
__device__ u64   g_Whp[32 * 192];
__device__ u64   g_Wr1p[32 * 128];
__device__ float g_bvec[192];

__device__ __forceinline__ float sigmoidf(float x) { return 1.f / (1.f + expf(-x)); }
__device__ __forceinline__ u64 pack2(float lo, float hi) {
    u64 r; asm("mov.b64 %0, {%1, %2};" : "=l"(r) : "f"(lo), "f"(hi)); return r;
}
__device__ __forceinline__ void unpack2(u64 v, float& lo, float& hi) {
    asm("mov.b64 {%0, %1}, %2;" : "=f"(lo), "=f"(hi) : "l"(v));
}
__device__ __forceinline__ float sum2(u64 v) {
    float lo, hi; unpack2(v, lo, hi); return lo + hi;
}
__device__ __forceinline__ u64 fma2(u64 a, u64 b, u64 c) {
    u64 d; asm("fma.rn.f32x2 %0, %1, %2, %3;" : "=l"(d) : "l"(a), "l"(b), "l"(c)); return d;
}

// ---------------------------------------------------------------------------
// Launch 0: init h/cnt + weight prep (C table eliminated — computed in agg).
// ---------------------------------------------------------------------------
__global__ __launch_bounds__(256) void mega_init_kernel(
    const float* __restrict__ nf, const float* __restrict__ W2,
    const float* __restrict__ Wx, const float* __restrict__ Wh,
    const float* __restrict__ Wr1, const float* __restrict__ b2)
{
    const int b   = blockIdx.x;
    const int tid = threadIdx.x;

    if (b < NB_INIT) {
        int i = b * 256 + tid;
        if (i < N_NODES * HDIM) g_h[i] = nf[i];
        if (i < N_NODES) g_cnt[i] = 0;
        return;
    }
    if (b < NB_INIT + NB_PWG) {
        int t = (b - NB_INIT) * 256 + tid;
        if (t < 64 * 192) {
            int k2 = t / 192, j = t % 192;
            float s0 = 0.f, s1 = 0.f;
            for (int c = 0; c < 64; c++) {
                float w = Wx[c * 192 + j];
                s0 = fmaf(W2[(2 * k2) * 64 + c], w, s0);
                s1 = fmaf(W2[(2 * k2 + 1) * 64 + c], w, s1);
            }
            g_Wg2[k2 * 192 + j] = pack2(s0, s1);
        }
        return;
    }
    {
        int t = (b - (NB_INIT + NB_PWG)) * 256 + tid;
        if (t < 32 * 192) {
            int i = t / 192, j = t % 192;
            g_Whp[t] = pack2(Wh[(2 * i) * 192 + j], Wh[(2 * i + 1) * 192 + j]);
        } else if (t < 32 * 192 + 32 * 128) {
            int u = t - 32 * 192;
            int i = u / 128, j = u % 128;
            g_Wr1p[u] = pack2(Wr1[(2 * i) * 128 + j], Wr1[(2 * i + 1) * 128 + j]);
        } else if (t < 32 * 192 + 32 * 128 + 192) {
            int j = t - (32 * 192 + 32 * 128);
            float s = 0.f;
            for (int c = 0; c < 64; c++) s = fmaf(b2[c], Wx[c * 192 + j], s);
            g_bvec[j] = s;
        }
    }
}

// ---------------------------------------------------------------------------
// Launch 1: ELL build + standalone projection into buffer 0.
// ---------------------------------------------------------------------------
__global__ __launch_bounds__(256) void build_proj_kernel(
    const int* __restrict__ src, const int* __restrict__ dst,
    const float* __restrict__ W1)
{
    const int b   = blockIdx.x;
    const int tid = threadIdx.x;

    if (b < NB_ELL) {
        int i = b * 256 + tid;
        if (i < N_EDGES) {
            int d = dst[i];
            int slot = atomicAdd(&g_cnt[d], 1);
            if (slot < MAXDEG)
                g_ell[(long)d * MAXDEG + slot] = make_int2(src[i], i);
        }
        return;
    }

    __shared__ float sh[PB][HDIM];
    const int n0 = (b - NB_ELL) * PB;

    for (int i = tid; i < PB * HDIM; i += 256) {
        int r = i >> 6, c = i & 63;
        int node = n0 + r;
        sh[r][c] = (node < N_NODES) ? g_h[(long)node * HDIM + c] : 0.f;
    }
    __syncthreads();

    const int hc = tid & 31;
    const int nr = tid >> 5;
    const int j0 = hc * 8;
    const float* Wbase = (j0 < 128) ? (W1 + j0) : (W1 + 64 * MHID + (j0 - 128));

    float acc[8][8];
    #pragma unroll
    for (int n = 0; n < 8; n++)
        #pragma unroll
        for (int j = 0; j < 8; j++) acc[n][j] = 0.f;

    #pragma unroll 2
    for (int k = 0; k < HDIM; k++) {
        const float4* wp = reinterpret_cast<const float4*>(Wbase + (long)k * MHID);
        float4 wA = wp[0], wB = wp[1];
        #pragma unroll
        for (int n = 0; n < 8; n++) {
            float a = sh[nr + 8 * n][k];
            acc[n][0] = fmaf(a, wA.x, acc[n][0]);
            acc[n][1] = fmaf(a, wA.y, acc[n][1]);
            acc[n][2] = fmaf(a, wA.z, acc[n][2]);
            acc[n][3] = fmaf(a, wA.w, acc[n][3]);
            acc[n][4] = fmaf(a, wB.x, acc[n][4]);
            acc[n][5] = fmaf(a, wB.y, acc[n][5]);
            acc[n][6] = fmaf(a, wB.z, acc[n][6]);
            acc[n][7] = fmaf(a, wB.w, acc[n][7]);
        }
    }

    #pragma unroll
    for (int n = 0; n < 8; n++) {
        int node = n0 + nr + 8 * n;
        if (node < N_NODES) {
            float* dstp = (j0 < 128) ? (g_PA[0] + (long)node * MHID + j0)
                                     : (g_PBuf[0] + (long)node * MHID + (j0 - 128));
            float4* op = reinterpret_cast<float4*>(dstp);
            op[0] = make_float4(acc[n][0], acc[n][1], acc[n][2], acc[n][3]);
            op[1] = make_float4(acc[n][4], acc[n][5], acc[n][6], acc[n][7]);
        }
    }
}

// ---------------------------------------------------------------------------
// Kernel A: ELL aggregation, C computed on the fly from ef + smem W1c.
//   agg[d][c] = sum_e relu(PA[src_e][c] + PB[d][c] + (ef[e]@W1c)[c] + b1[c])
// One warp per node; lane owns cols 4*lane..4*lane+3.
// ---------------------------------------------------------------------------
__global__ __launch_bounds__(256) void agg_kernel(
    const float* __restrict__ ef, const float* __restrict__ W1,
    const float* __restrict__ b1, int rbuf)
{
    __shared__ float sW1c[EDIM][MHID];
    __shared__ float sb1[MHID];
    const int tid  = threadIdx.x;
    const int lane = tid & 31;
    const int wid  = tid >> 5;

    for (int i = tid; i < EDIM * MHID; i += 256)
        sW1c[i >> 7][i & 127] = W1[128 * MHID + i];
    if (tid < MHID) sb1[tid] = b1[tid];
    __syncthreads();

    const int node = blockIdx.x * 8 + wid;
    if (node >= N_NODES) return;

    const float* PAr = g_PA[rbuf];
    const float* PBr = g_PBuf[rbuf];

    int dg = g_cnt[node];
    if (dg > MAXDEG) dg = MAXDEG;

    const int c0 = 4 * lane;
    float4 pb = *reinterpret_cast<const float4*>(PBr + (long)node * MHID + c0);
    float bb0 = sb1[c0], bb1 = sb1[c0 + 1], bb2 = sb1[c0 + 2], bb3 = sb1[c0 + 3];
    float4 acc = make_float4(0.f, 0.f, 0.f, 0.f);
    const int2* ep = g_ell + (long)node * MAXDEG;

    for (int s = 0; s < dg; s++) {
        int2 e = ep[s];
        float4 pa = *reinterpret_cast<const float4*>(PAr + (long)e.x * MHID + c0);
        // ef row: 8 floats, broadcast loads (all lanes same address)
        const float4* efp = reinterpret_cast<const float4*>(ef + (long)e.y * EDIM);
        float4 e0 = efp[0], e1 = efp[1];
        float efr[EDIM] = { e0.x, e0.y, e0.z, e0.w, e1.x, e1.y, e1.z, e1.w };
        float v0 = bb0, v1 = bb1, v2 = bb2, v3 = bb3;
        #pragma unroll
        for (int k = 0; k < EDIM; k++) {
            float ek = efr[k];
            v0 = fmaf(ek, sW1c[k][c0 + 0], v0);
            v1 = fmaf(ek, sW1c[k][c0 + 1], v1);
            v2 = fmaf(ek, sW1c[k][c0 + 2], v2);
            v3 = fmaf(ek, sW1c[k][c0 + 3], v3);
        }
        acc.x += fmaxf(pa.x + pb.x + v0, 0.f);
        acc.y += fmaxf(pa.y + pb.y + v1, 0.f);
        acc.z += fmaxf(pa.z + pb.z + v2, 0.f);
        acc.w += fmaxf(pa.w + pb.w + v3, 0.f);
    }
    *reinterpret_cast<float4*>(g_agg + (long)node * MHID + c0) = acc;
}

// ---------------------------------------------------------------------------
// Kernel B: gates GEMM + GRU + (proj | readout), column-split.
// Warp pair wp = wid>>1 owns 8 nodes {wp+4n}; jh = wid&1 owns one column half.
// Per k2 the warp loads HALF the weights of the R14 version.
// ---------------------------------------------------------------------------
__global__ __launch_bounds__(256, 2) void gru_fused_kernel(
    const float* __restrict__ bg, const float* __restrict__ W1,
    const float* __restrict__ br1, const float* __restrict__ Wr2,
    const float* __restrict__ br2, float* __restrict__ out,
    int rbuf, int do_proj)
{
    __shared__ float sxh[GB][192];    // cols 0..127 agg128, 128..191 h_old
    __shared__ int   sdeg[GB];
    __shared__ float spart[GB][2];
    const int tid  = threadIdx.x;
    const int lane = tid & 31;
    const int wid  = tid >> 5;
    const int wp   = wid >> 1;        // 0..3: row group
    const int jh   = wid & 1;         // column half
    const int n0   = blockIdx.x * GB;

    // --- stage agg + h + deg (warp w stages rows w+8n) ---
    #pragma unroll
    for (int n = 0; n < 4; n++) {
        const int r = wid + 8 * n;
        const int node = n0 + r;
        if (node < N_NODES) {
            *reinterpret_cast<float4*>(&sxh[r][4 * lane]) =
                *reinterpret_cast<const float4*>(g_agg + (long)node * MHID + 4 * lane);
            float2 hv = *reinterpret_cast<const float2*>(g_h + (long)node * HDIM + 2 * lane);
            sxh[r][128 + 2 * lane]     = hv.x;
            sxh[r][128 + 2 * lane + 1] = hv.y;
            if (lane == 0) sdeg[r] = min(g_cnt[node], MAXDEG);
        } else {
            *reinterpret_cast<float4*>(&sxh[r][4 * lane]) = make_float4(0.f, 0.f, 0.f, 0.f);
            sxh[r][128 + 2 * lane]     = 0.f;
            sxh[r][128 + 2 * lane + 1] = 0.f;
            if (lane == 0) sdeg[r] = 0;
        }
    }
    __syncthreads();

    const int co = lane + 32 * jh;    // owned column within each 64-col gate block

    // --- gates GEMM: 8 nodes x {z, r, cx, ch} k-split accumulators ---
    u64 az[8], ar[8], acx[8], ach[8];
    #pragma unroll
    for (int n = 0; n < 8; n++) { az[n] = 0ull; ar[n] = 0ull; acx[n] = 0ull; ach[n] = 0ull; }

    #pragma unroll 2
    for (int k2 = 0; k2 < 64; k2++) {        // agg128 @ WgA
        const u64* wr = g_Wg2 + k2 * 192;
        u64 wz = wr[co], wrr = wr[64 + co], wc = wr[128 + co];
        #pragma unroll
        for (int n = 0; n < 8; n++) {
            u64 a = *reinterpret_cast<const u64*>(&sxh[wp + 4 * n][2 * k2]);
            az[n]  = fma2(a, wz,  az[n]);
            ar[n]  = fma2(a, wrr, ar[n]);
            acx[n] = fma2(a, wc,  acx[n]);
        }
    }
    #pragma unroll 2
    for (int k2 = 0; k2 < 32; k2++) {        // h @ Wh
        const u64* wr = g_Whp + k2 * 192;
        u64 wz = wr[co], wrr = wr[64 + co], wc = wr[128 + co];
        #pragma unroll
        for (int n = 0; n < 8; n++) {
            u64 a = *reinterpret_cast<const u64*>(&sxh[wp + 4 * n][128 + 2 * k2]);
            az[n]  = fma2(a, wz,  az[n]);
            ar[n]  = fma2(a, wrr, ar[n]);
            ach[n] = fma2(a, wc,  ach[n]);
        }
    }
    __syncthreads();   // partner warp's GEMM reads of agg region must finish

    // --- elementwise GRU (thread owns col co of its 8 nodes) ---
    {
        float bz = bg[co],       vz = g_bvec[co];
        float brg = bg[64 + co], vr = g_bvec[64 + co];
        float bc = bg[128 + co], vc = g_bvec[128 + co];

        #pragma unroll
        for (int n = 0; n < 8; n++) {
            int r = wp + 4 * n;
            int node = n0 + r;
            float deg = (float)sdeg[r];
            float z  = sigmoidf(sum2(az[n]) + bz + deg * vz);
            float rr = sigmoidf(sum2(ar[n]) + brg + deg * vr);
            float hc = tanhf(sum2(acx[n]) + bc + deg * vc + rr * sum2(ach[n]));
            float hold = sxh[r][128 + co];
            float hnew = z * hold + (1.f - z) * hc;
            sxh[r][co] = hnew;
            if (node < N_NODES) g_h[(long)node * HDIM + co] = hnew;
        }
    }
    __syncthreads();   // proj/readout read the full h_new rows

    if (do_proj) {
        // warp jh=0 -> PA (W1 rows 0..63), jh=1 -> PB (W1 rows 64..127)
        float* Pw = (jh ? g_PBuf[rbuf ^ 1] : g_PA[rbuf ^ 1]);
        const int rowbase = jh * 64;
        u64 p0[8], p1[8];
        #pragma unroll
        for (int n = 0; n < 8; n++) { p0[n] = 0ull; p1[n] = 0ull; }

        #pragma unroll 2
        for (int k = 0; k < 64; k++) {
            const float* wrow = W1 + (long)(rowbase + k) * MHID;
            u64 w0 = *reinterpret_cast<const u64*>(wrow + 2 * lane);
            u64 w1 = *reinterpret_cast<const u64*>(wrow + 64 + 2 * lane);
            #pragma unroll
            for (int n = 0; n < 8; n++) {
                float af = sxh[wp + 4 * n][k];
                u64 ap = pack2(af, af);
                p0[n] = fma2(ap, w0, p0[n]);
                p1[n] = fma2(ap, w1, p1[n]);
            }
        }
        #pragma unroll
        for (int n = 0; n < 8; n++) {
            int node = n0 + wp + 4 * n;
            if (node < N_NODES) {
                float* dp = Pw + (long)node * MHID;
                *reinterpret_cast<u64*>(dp + 2 * lane)      = p0[n];
                *reinterpret_cast<u64*>(dp + 64 + 2 * lane) = p1[n];
            }
        }
    } else {
        // readout: warp jh owns Wr1 cols [64*jh, 64*jh+64)
        u64 rc0[8], rc1[8];
        #pragma unroll
        for (int n = 0; n < 8; n++) { rc0[n] = 0ull; rc1[n] = 0ull; }

        #pragma unroll 2
        for (int k2 = 0; k2 < 32; k2++) {
            const u64* wr = g_Wr1p + k2 * 128 + 64 * jh;
            u64 w0 = wr[lane], w1 = wr[lane + 32];
            #pragma unroll
            for (int n = 0; n < 8; n++) {
                u64 a = *reinterpret_cast<const u64*>(&sxh[wp + 4 * n][2 * k2]);
                rc0[n] = fma2(a, w0, rc0[n]);
                rc1[n] = fma2(a, w1, rc1[n]);
            }
        }
        float bb0 = br1[64 * jh + lane],  bb1 = br1[64 * jh + 32 + lane];
        float wv0 = Wr2[64 * jh + lane],  wv1 = Wr2[64 * jh + 32 + lane];

        #pragma unroll
        for (int n = 0; n < 8; n++) {
            float s = fmaxf(sum2(rc0[n]) + bb0, 0.f) * wv0
                    + fmaxf(sum2(rc1[n]) + bb1, 0.f) * wv1;
            #pragma unroll
            for (int off = 16; off; off >>= 1)
                s += __shfl_xor_sync(0xffffffffu, s, off);
            if (lane == 0) spart[wp + 4 * n][jh] = s;
        }
        __syncthreads();
        if (tid < GB) {
            int node = n0 + tid;
            if (node < N_NODES)
                out[node] = spart[tid][0] + spart[tid][1] + br2[0];
        }
    }
}

extern "C" void kernel_launch(void* const* d_in, const int* in_sizes, int n_in,
                              void* d_out, int out_size) {
    const float* nf  = (const float*)d_in[0];
    const float* ef  = (const float*)d_in[1];
    const int*   src = (const int*)  d_in[2];
    const int*   dst = (const int*)  d_in[3];
    const float* W1  = (const float*)d_in[4];
    const float* b1  = (const float*)d_in[5];
    const float* W2  = (const float*)d_in[6];
    const float* b2  = (const float*)d_in[7];
    const float* Wx  = (const float*)d_in[8];
    const float* Wh  = (const float*)d_in[9];
    const float* bg  = (const float*)d_in[10];
    const float* Wr1 = (const float*)d_in[11];
    const float* br1 = (const float*)d_in[12];
    const float* Wr2 = (const float*)d_in[13];
    const float* br2 = (const float*)d_in[14];
    float* out = (float*)d_out;

    const int ngru = (N_NODES + GB - 1) / GB;      // 1563
    const int nagg = (N_NODES + 7) / 8;            // 6250

    // launch idx 0
    mega_init_kernel<<<NB_INIT + NB_PWG + NB_PPK, 256>>>(nf, W2, Wx, Wh, Wr1, b2);
    // launch idx 1
    build_proj_kernel<<<NB_ELL + NB_PROJ, 256>>>(src, dst, W1);
    // t = 0
    agg_kernel<<<nagg, 256>>>(ef, W1, b1, 0);                            // idx 2
    gru_fused_kernel<<<ngru, 256>>>(bg, W1, br1, Wr2, br2, out, 0, 1);   // idx 3 (ncu slot)
    // t = 1
    agg_kernel<<<nagg, 256>>>(ef, W1, b1, 1);                            // idx 4
    gru_fused_kernel<<<ngru, 256>>>(bg, W1, br1, Wr2, br2, out, 1, 0);   // idx 5
}

// round 16
// speedup vs baseline: 1.7243x; 1.0655x over previous
#include <cuda_runtime.h>
#include <cuda_bf16.h>
#include <math.h>

#define N_NODES 50000
#define N_EDGES 400000
#define HDIM 64
#define EDIM 8
#define MHID 128
#define RHID 128
#define PB 64      // nodes per block in projection branch
#define GB 32      // nodes per block in GEMM/GRU kernel (8 per warp-pair)
#define MAXDEG 64  // ELL width; P(Poisson(8) >= 64) ~ 1e-36

typedef unsigned long long u64;

// Grid partition constants
#define NB_INIT  12500
#define NB_PWG   48     // 64*192 = 12288 threads
#define NB_PPK   73     // 6144 + 4096 + 8192 + 192 = 18624 threads
#define NB_ELL   1563
#define NB_PROJ  782

// Scratch (device globals: no allocation allowed)
__device__ float g_h[N_NODES * HDIM];
__device__ float g_PA[2][N_NODES * MHID];
__device__ float g_PBuf[2][N_NODES * MHID];
__device__ float g_agg[N_NODES * MHID];
__device__ int   g_cnt[N_NODES];
__device__ int2  g_ell[(long)N_NODES * MAXDEG];   // (src, edge_id)
// k-quad interleaved weight layouts (all loads LDG.128):
__device__ ulonglong2 g_Wg2p[32 * 192];   // [k4][col]: (k4k+0,1 | k4k+2,3) pairs
__device__ ulonglong2 g_Whpp[16 * 192];   // same for Wh
__device__ ulonglong2 g_Wr1pp[32 * 64];   // [k2][jh*32+lane]: two col-group pairs
__device__ ulonglong2 g_W1pp[2 * 32 * 32 * 2]; // [jh][kk][lane][2]: k-split col quads
__device__ float g_bvec[192];

__device__ __forceinline__ float sigmoidf(float x) { return 1.f / (1.f + expf(-x)); }
__device__ __forceinline__ u64 pack2(float lo, float hi) {
    u64 r; asm("mov.b64 %0, {%1, %2};" : "=l"(r) : "f"(lo), "f"(hi)); return r;
}
__device__ __forceinline__ void unpack2(u64 v, float& lo, float& hi) {
    asm("mov.b64 {%0, %1}, %2;" : "=f"(lo), "=f"(hi) : "l"(v));
}
__device__ __forceinline__ float sum2(u64 v) {
    float lo, hi; unpack2(v, lo, hi); return lo + hi;
}
__device__ __forceinline__ u64 fma2(u64 a, u64 b, u64 c) {
    u64 d; asm("fma.rn.f32x2 %0, %1, %2, %3;" : "=l"(d) : "l"(a), "l"(b), "l"(c)); return d;
}

// ---------------------------------------------------------------------------
// Launch 0: init h/cnt + weight prep into 128-bit layouts.
// ---------------------------------------------------------------------------
__global__ __launch_bounds__(256) void mega_init_kernel(
    const float* __restrict__ nf, const float* __restrict__ W1,
    const float* __restrict__ W2, const float* __restrict__ Wx,
    const float* __restrict__ Wh, const float* __restrict__ Wr1,
    const float* __restrict__ b2)
{
    const int b   = blockIdx.x;
    const int tid = threadIdx.x;

    if (b < NB_INIT) {
        int i = b * 256 + tid;
        if (i < N_NODES * HDIM) g_h[i] = nf[i];
        if (i < N_NODES) g_cnt[i] = 0;
        return;
    }
    if (b < NB_INIT + NB_PWG) {
        // WgA = W2 @ Wx, k2 rows -> k-quad interleaved slots
        int t = (b - NB_INIT) * 256 + tid;
        if (t < 64 * 192) {
            int k2 = t / 192, j = t % 192;
            float s0 = 0.f, s1 = 0.f;
            for (int c = 0; c < 64; c++) {
                float w = Wx[c * 192 + j];
                s0 = fmaf(W2[(2 * k2) * 64 + c], w, s0);
                s1 = fmaf(W2[(2 * k2 + 1) * 64 + c], w, s1);
            }
            reinterpret_cast<u64*>(g_Wg2p)[(((k2 >> 1) * 192 + j) << 1) + (k2 & 1)] =
                pack2(s0, s1);
        }
        return;
    }
    {
        int t = (b - (NB_INIT + NB_PWG)) * 256 + tid;
        if (t < 32 * 192) {
            int k2 = t / 192, j = t % 192;
            reinterpret_cast<u64*>(g_Whpp)[(((k2 >> 1) * 192 + j) << 1) + (k2 & 1)] =
                pack2(Wh[(2 * k2) * 192 + j], Wh[(2 * k2 + 1) * 192 + j]);
        } else if (t < 32 * 192 + 32 * 128) {
            int u = t - 32 * 192;
            int k2 = u / 128, j = u % 128;
            int jh = j >> 6, within = j & 63;
            int p = jh * 32 + (within & 31);
            int slot = within >> 5;
            reinterpret_cast<u64*>(g_Wr1pp)[((k2 * 64 + p) << 1) + slot] =
                pack2(Wr1[(2 * k2) * 128 + j], Wr1[(2 * k2 + 1) * 128 + j]);
        } else if (t < 32 * 192 + 32 * 128 + 8192) {
            // W1 proj weights, k-split col quads: t = ((jh*32+kk)*32+lane)*4+cs
            int u  = t - (32 * 192 + 32 * 128);
            int jh = u >> 12;
            int kk = (u >> 7) & 31;
            int lane = (u >> 2) & 31;
            int cs = u & 3;
            int c  = 4 * lane + cs;
            int r0 = jh * 64 + 2 * kk;
            reinterpret_cast<u64*>(g_W1pp)[u] =
                pack2(W1[(long)r0 * MHID + c], W1[(long)(r0 + 1) * MHID + c]);
        } else if (t < 32 * 192 + 32 * 128 + 8192 + 192) {
            int j = t - (32 * 192 + 32 * 128 + 8192);
            float s = 0.f;
            for (int c = 0; c < 64; c++) s = fmaf(b2[c], Wx[c * 192 + j], s);
            g_bvec[j] = s;
        }
    }
}

// ---------------------------------------------------------------------------
// Launch 1: ELL build + standalone projection into buffer 0.
// ---------------------------------------------------------------------------
__global__ __launch_bounds__(256) void build_proj_kernel(
    const int* __restrict__ src, const int* __restrict__ dst,
    const float* __restrict__ W1)
{
    const int b   = blockIdx.x;
    const int tid = threadIdx.x;

    if (b < NB_ELL) {
        int i = b * 256 + tid;
        if (i < N_EDGES) {
            int d = dst[i];
            int slot = atomicAdd(&g_cnt[d], 1);
            if (slot < MAXDEG)
                g_ell[(long)d * MAXDEG + slot] = make_int2(src[i], i);
        }
        return;
    }

    __shared__ float sh[PB][HDIM];
    const int n0 = (b - NB_ELL) * PB;

    for (int i = tid; i < PB * HDIM; i += 256) {
        int r = i >> 6, c = i & 63;
        int node = n0 + r;
        sh[r][c] = (node < N_NODES) ? g_h[(long)node * HDIM + c] : 0.f;
    }
    __syncthreads();

    const int hc = tid & 31;
    const int nr = tid >> 5;
    const int j0 = hc * 8;
    const float* Wbase = (j0 < 128) ? (W1 + j0) : (W1 + 64 * MHID + (j0 - 128));

    float acc[8][8];
    #pragma unroll
    for (int n = 0; n < 8; n++)
        #pragma unroll
        for (int j = 0; j < 8; j++) acc[n][j] = 0.f;

    #pragma unroll 2
    for (int k = 0; k < HDIM; k++) {
        const float4* wp = reinterpret_cast<const float4*>(Wbase + (long)k * MHID);
        float4 wA = wp[0], wB = wp[1];
        #pragma unroll
        for (int n = 0; n < 8; n++) {
            float a = sh[nr + 8 * n][k];
            acc[n][0] = fmaf(a, wA.x, acc[n][0]);
            acc[n][1] = fmaf(a, wA.y, acc[n][1]);
            acc[n][2] = fmaf(a, wA.z, acc[n][2]);
            acc[n][3] = fmaf(a, wA.w, acc[n][3]);
            acc[n][4] = fmaf(a, wB.x, acc[n][4]);
            acc[n][5] = fmaf(a, wB.y, acc[n][5]);
            acc[n][6] = fmaf(a, wB.z, acc[n][6]);
            acc[n][7] = fmaf(a, wB.w, acc[n][7]);
        }
    }

    #pragma unroll
    for (int n = 0; n < 8; n++) {
        int node = n0 + nr + 8 * n;
        if (node < N_NODES) {
            float* dstp = (j0 < 128) ? (g_PA[0] + (long)node * MHID + j0)
                                     : (g_PBuf[0] + (long)node * MHID + (j0 - 128));
            float4* op = reinterpret_cast<float4*>(dstp);
            op[0] = make_float4(acc[n][0], acc[n][1], acc[n][2], acc[n][3]);
            op[1] = make_float4(acc[n][4], acc[n][5], acc[n][6], acc[n][7]);
        }
    }
}

// ---------------------------------------------------------------------------
// Kernel A: ELL aggregation, C computed on the fly (unchanged from R15).
// ---------------------------------------------------------------------------
__global__ __launch_bounds__(256) void agg_kernel(
    const float* __restrict__ ef, const float* __restrict__ W1,
    const float* __restrict__ b1, int rbuf)
{
    __shared__ float sW1c[EDIM][MHID];
    __shared__ float sb1[MHID];
    const int tid  = threadIdx.x;
    const int lane = tid & 31;
    const int wid  = tid >> 5;

    for (int i = tid; i < EDIM * MHID; i += 256)
        sW1c[i >> 7][i & 127] = W1[128 * MHID + i];
    if (tid < MHID) sb1[tid] = b1[tid];
    __syncthreads();

    const int node = blockIdx.x * 8 + wid;
    if (node >= N_NODES) return;

    const float* PAr = g_PA[rbuf];
    const float* PBr = g_PBuf[rbuf];

    int dg = g_cnt[node];
    if (dg > MAXDEG) dg = MAXDEG;

    const int c0 = 4 * lane;
    float4 pb = *reinterpret_cast<const float4*>(PBr + (long)node * MHID + c0);
    float bb0 = sb1[c0], bb1 = sb1[c0 + 1], bb2 = sb1[c0 + 2], bb3 = sb1[c0 + 3];
    float4 acc = make_float4(0.f, 0.f, 0.f, 0.f);
    const int2* ep = g_ell + (long)node * MAXDEG;

    for (int s = 0; s < dg; s++) {
        int2 e = ep[s];
        float4 pa = *reinterpret_cast<const float4*>(PAr + (long)e.x * MHID + c0);
        const float4* efp = reinterpret_cast<const float4*>(ef + (long)e.y * EDIM);
        float4 e0 = efp[0], e1 = efp[1];
        float efr[EDIM] = { e0.x, e0.y, e0.z, e0.w, e1.x, e1.y, e1.z, e1.w };
        float v0 = bb0, v1 = bb1, v2 = bb2, v3 = bb3;
        #pragma unroll
        for (int k = 0; k < EDIM; k++) {
            float ek = efr[k];
            v0 = fmaf(ek, sW1c[k][c0 + 0], v0);
            v1 = fmaf(ek, sW1c[k][c0 + 1], v1);
            v2 = fmaf(ek, sW1c[k][c0 + 2], v2);
            v3 = fmaf(ek, sW1c[k][c0 + 3], v3);
        }
        acc.x += fmaxf(pa.x + pb.x + v0, 0.f);
        acc.y += fmaxf(pa.y + pb.y + v1, 0.f);
        acc.z += fmaxf(pa.z + pb.z + v2, 0.f);
        acc.w += fmaxf(pa.w + pb.w + v3, 0.f);
    }
    *reinterpret_cast<float4*>(g_agg + (long)node * MHID + c0) = acc;
}

// ---------------------------------------------------------------------------
// Kernel B: gates GEMM + GRU + (proj | readout), column-split, 128-bit loads.
// Warp pair wp owns 8 nodes {wp+4n}; jh = wid&1 owns one column half.
// ---------------------------------------------------------------------------
__global__ __launch_bounds__(256, 2) void gru_fused_kernel(
    const float* __restrict__ bg, const float* __restrict__ br1,
    const float* __restrict__ Wr2, const float* __restrict__ br2,
    float* __restrict__ out, int rbuf, int do_proj)
{
    __shared__ float sxh[GB][192];    // cols 0..127 agg128, 128..191 h_old
    __shared__ int   sdeg[GB];
    __shared__ float spart[GB][2];
    const int tid  = threadIdx.x;
    const int lane = tid & 31;
    const int wid  = tid >> 5;
    const int wp   = wid >> 1;
    const int jh   = wid & 1;
    const int n0   = blockIdx.x * GB;

    // --- stage agg + h + deg ---
    #pragma unroll
    for (int n = 0; n < 4; n++) {
        const int r = wid + 8 * n;
        const int node = n0 + r;
        if (node < N_NODES) {
            *reinterpret_cast<float4*>(&sxh[r][4 * lane]) =
                *reinterpret_cast<const float4*>(g_agg + (long)node * MHID + 4 * lane);
            float2 hv = *reinterpret_cast<const float2*>(g_h + (long)node * HDIM + 2 * lane);
            sxh[r][128 + 2 * lane]     = hv.x;
            sxh[r][128 + 2 * lane + 1] = hv.y;
            if (lane == 0) sdeg[r] = min(g_cnt[node], MAXDEG);
        } else {
            *reinterpret_cast<float4*>(&sxh[r][4 * lane]) = make_float4(0.f, 0.f, 0.f, 0.f);
            sxh[r][128 + 2 * lane]     = 0.f;
            sxh[r][128 + 2 * lane + 1] = 0.f;
            if (lane == 0) sdeg[r] = 0;
        }
    }
    __syncthreads();

    const int co = lane + 32 * jh;

    // --- gates GEMM: k-quad iterations, all 128-bit loads ---
    u64 az[8], ar[8], acx[8], ach[8];
    #pragma unroll
    for (int n = 0; n < 8; n++) { az[n] = 0ull; ar[n] = 0ull; acx[n] = 0ull; ach[n] = 0ull; }

    #pragma unroll 2
    for (int k4 = 0; k4 < 32; k4++) {        // agg128 @ WgA (4 k per iter)
        const ulonglong2* wrp = g_Wg2p + k4 * 192;
        ulonglong2 wz = wrp[co], wrr = wrp[64 + co], wc = wrp[128 + co];
        #pragma unroll
        for (int n = 0; n < 8; n++) {
            ulonglong2 a = *reinterpret_cast<const ulonglong2*>(&sxh[wp + 4 * n][4 * k4]);
            az[n]  = fma2(a.x, wz.x,  az[n]);  az[n]  = fma2(a.y, wz.y,  az[n]);
            ar[n]  = fma2(a.x, wrr.x, ar[n]);  ar[n]  = fma2(a.y, wrr.y, ar[n]);
            acx[n] = fma2(a.x, wc.x,  acx[n]); acx[n] = fma2(a.y, wc.y,  acx[n]);
        }
    }
    #pragma unroll 2
    for (int k4 = 0; k4 < 16; k4++) {        // h @ Wh
        const ulonglong2* wrp = g_Whpp + k4 * 192;
        ulonglong2 wz = wrp[co], wrr = wrp[64 + co], wc = wrp[128 + co];
        #pragma unroll
        for (int n = 0; n < 8; n++) {
            ulonglong2 a = *reinterpret_cast<const ulonglong2*>(&sxh[wp + 4 * n][128 + 4 * k4]);
            az[n]  = fma2(a.x, wz.x,  az[n]);  az[n]  = fma2(a.y, wz.y,  az[n]);
            ar[n]  = fma2(a.x, wrr.x, ar[n]);  ar[n]  = fma2(a.y, wrr.y, ar[n]);
            ach[n] = fma2(a.x, wc.x,  ach[n]); ach[n] = fma2(a.y, wc.y,  ach[n]);
        }
    }
    __syncthreads();

    // --- elementwise GRU ---
    {
        float bz = bg[co],       vz = g_bvec[co];
        float brg = bg[64 + co], vr = g_bvec[64 + co];
        float bc = bg[128 + co], vc = g_bvec[128 + co];

        #pragma unroll
        for (int n = 0; n < 8; n++) {
            int r = wp + 4 * n;
            int node = n0 + r;
            float deg = (float)sdeg[r];
            float z  = sigmoidf(sum2(az[n]) + bz + deg * vz);
            float rr = sigmoidf(sum2(ar[n]) + brg + deg * vr);
            float hc = tanhf(sum2(acx[n]) + bc + deg * vc + rr * sum2(ach[n]));
            float hold = sxh[r][128 + co];
            float hnew = z * hold + (1.f - z) * hc;
            sxh[r][co] = hnew;
            if (node < N_NODES) g_h[(long)node * HDIM + co] = hnew;
        }
    }
    __syncthreads();

    if (do_proj) {
        // warp jh=0 -> PA, jh=1 -> PB; thread owns cols 4*lane..4*lane+3,
        // k-split u64 accumulator per col, paired-k weights (LDG.128).
        float* Pw = (jh ? g_PBuf[rbuf ^ 1] : g_PA[rbuf ^ 1]);
        u64 p[8][4];
        #pragma unroll
        for (int n = 0; n < 8; n++)
            #pragma unroll
            for (int j = 0; j < 4; j++) p[n][j] = 0ull;

        #pragma unroll 2
        for (int kk = 0; kk < 32; kk++) {
            const ulonglong2* wq = g_W1pp + (((jh << 5) + kk) << 5 | lane) * 2;
            ulonglong2 wA = wq[0], wB = wq[1];
            #pragma unroll
            for (int n = 0; n < 8; n++) {
                u64 a = *reinterpret_cast<const u64*>(&sxh[wp + 4 * n][2 * kk]);
                p[n][0] = fma2(a, wA.x, p[n][0]);
                p[n][1] = fma2(a, wA.y, p[n][1]);
                p[n][2] = fma2(a, wB.x, p[n][2]);
                p[n][3] = fma2(a, wB.y, p[n][3]);
            }
        }
        #pragma unroll
        for (int n = 0; n < 8; n++) {
            int node = n0 + wp + 4 * n;
            if (node < N_NODES) {
                float4 ov = make_float4(sum2(p[n][0]), sum2(p[n][1]),
                                        sum2(p[n][2]), sum2(p[n][3]));
                *reinterpret_cast<float4*>(Pw + (long)node * MHID + 4 * lane) = ov;
            }
        }
    } else {
        // readout: warp jh owns Wr1 cols [64*jh, 64*jh+64), paired LDG.128
        u64 rc0[8], rc1[8];
        #pragma unroll
        for (int n = 0; n < 8; n++) { rc0[n] = 0ull; rc1[n] = 0ull; }

        #pragma unroll 2
        for (int k2 = 0; k2 < 32; k2++) {
            ulonglong2 w = g_Wr1pp[k2 * 64 + jh * 32 + lane];
            #pragma unroll
            for (int n = 0; n < 8; n++) {
                u64 a = *reinterpret_cast<const u64*>(&sxh[wp + 4 * n][2 * k2]);
                rc0[n] = fma2(a, w.x, rc0[n]);
                rc1[n] = fma2(a, w.y, rc1[n]);
            }
        }
        float bb0 = br1[64 * jh + lane],  bb1 = br1[64 * jh + 32 + lane];
        float wv0 = Wr2[64 * jh + lane],  wv1 = Wr2[64 * jh + 32 + lane];

        #pragma unroll
        for (int n = 0; n < 8; n++) {
            float s = fmaxf(sum2(rc0[n]) + bb0, 0.f) * wv0
                    + fmaxf(sum2(rc1[n]) + bb1, 0.f) * wv1;
            #pragma unroll
            for (int off = 16; off; off >>= 1)
                s += __shfl_xor_sync(0xffffffffu, s, off);
            if (lane == 0) spart[wp + 4 * n][jh] = s;
        }
        __syncthreads();
        if (tid < GB) {
            int node = n0 + tid;
            if (node < N_NODES)
                out[node] = spart[tid][0] + spart[tid][1] + br2[0];
        }
    }
}

extern "C" void kernel_launch(void* const* d_in, const int* in_sizes, int n_in,
                              void* d_out, int out_size) {
    const float* nf  = (const float*)d_in[0];
    const float* ef  = (const float*)d_in[1];
    const int*   src = (const int*)  d_in[2];
    const int*   dst = (const int*)  d_in[3];
    const float* W1  = (const float*)d_in[4];
    const float* b1  = (const float*)d_in[5];
    const float* W2  = (const float*)d_in[6];
    const float* b2  = (const float*)d_in[7];
    const float* Wx  = (const float*)d_in[8];
    const float* Wh  = (const float*)d_in[9];
    const float* bg  = (const float*)d_in[10];
    const float* Wr1 = (const float*)d_in[11];
    const float* br1 = (const float*)d_in[12];
    const float* Wr2 = (const float*)d_in[13];
    const float* br2 = (const float*)d_in[14];
    float* out = (float*)d_out;

    const int ngru = (N_NODES + GB - 1) / GB;      // 1563
    const int nagg = (N_NODES + 7) / 8;            // 6250

    // launch idx 0
    mega_init_kernel<<<NB_INIT + NB_PWG + NB_PPK, 256>>>(nf, W1, W2, Wx, Wh, Wr1, b2);
    // launch idx 1
    build_proj_kernel<<<NB_ELL + NB_PROJ, 256>>>(src, dst, W1);
    // t = 0
    agg_kernel<<<nagg, 256>>>(ef, W1, b1, 0);                        // idx 2
    gru_fused_kernel<<<ngru, 256>>>(bg, br1, Wr2, br2, out, 0, 1);   // idx 3 (ncu slot)
    // t = 1
    agg_kernel<<<nagg, 256>>>(ef, W1, b1, 1);                        // idx 4
    gru_fused_kernel<<<ngru, 256>>>(bg, br1, Wr2, br2, out, 1, 0);   // idx 5
}